// round 12
// baseline (speedup 1.0000x reference)
#include <cuda_runtime.h>
#include <cuda_bf16.h>
#include <cstdint>

#define Bb 32
#define Nn 1024
#define Ff 3
#define Tt 32
#define Kk 3
#define Cc 64
#define Ct 64
#define FT (Ff*Tt)   // 96

// Scratch
__device__ float gY[(size_t)Bb * Kk * Nn * FT];            // 37.7 MB
__device__ __nv_bfloat16 gAh[(size_t)Kk * Nn * Nn];        // cheb^T hi [k][n][m]
__device__ __nv_bfloat16 gAl[(size_t)Kk * Nn * Nn];        // cheb^T lo
__device__ __nv_bfloat16 gXh[(size_t)Bb * FT * Nn];        // x^T hi [b][ft][m]
__device__ __nv_bfloat16 gXl[(size_t)Bb * FT * Nn];        // x^T lo
__device__ __align__(16) __nv_bfloat16 gWtH[3 * 64 * 72];  // W per-tap hi [tap][c][72]
__device__ __align__(16) __nv_bfloat16 gWtL[3 * 64 * 72];  // W per-tap lo

__device__ __forceinline__ uint32_t s2u(const void* p) {
    uint32_t a;
    asm("{ .reg .u64 t; cvta.to.shared.u64 t, %1; cvt.u32.u64 %0, t; }" : "=r"(a) : "l"(p));
    return a;
}

__device__ __forceinline__ void cp16(uint32_t dst, const void* src) {
    asm volatile("cp.async.cg.shared.global [%0], [%1], 16;" :: "r"(dst), "l"(src));
}
__device__ __forceinline__ void ldmx4(uint32_t* r, uint32_t addr) {
    asm volatile("ldmatrix.sync.aligned.m8n8.x4.shared.b16 {%0,%1,%2,%3}, [%4];"
                 : "=r"(r[0]), "=r"(r[1]), "=r"(r[2]), "=r"(r[3]) : "r"(addr));
}
__device__ __forceinline__ void mma16816(float* d, const uint32_t* a,
                                         uint32_t b0, uint32_t b1) {
    asm volatile(
        "mma.sync.aligned.m16n8k16.row.col.f32.bf16.bf16.f32 "
        "{%0,%1,%2,%3}, {%4,%5,%6,%7}, {%8,%9}, {%0,%1,%2,%3};"
        : "+f"(d[0]), "+f"(d[1]), "+f"(d[2]), "+f"(d[3])
        : "r"(a[0]), "r"(a[1]), "r"(a[2]), "r"(a[3]), "r"(b0), "r"(b1));
}

// ---------------------------------------------------------------------------
// Prep kernels (unchanged)
// ---------------------------------------------------------------------------
__global__ __launch_bounds__(256) void convert_cheb(const float* __restrict__ cheb)
{
    __shared__ float t[32][33];
    const int k = blockIdx.z, m0 = blockIdx.x * 32, n0 = blockIdx.y * 32;
    const int tx = threadIdx.x, ty = threadIdx.y;
    #pragma unroll
    for (int j = 0; j < 4; ++j)
        t[ty + j * 8][tx] = cheb[((size_t)(k * Nn + m0 + ty + j * 8)) * Nn + n0 + tx];
    __syncthreads();
    #pragma unroll
    for (int j = 0; j < 4; ++j) {
        const int n = n0 + ty + j * 8, m = m0 + tx;
        float v = t[tx][ty + j * 8];
        __nv_bfloat16 h = __float2bfloat16(v);
        __nv_bfloat16 l = __float2bfloat16(v - __bfloat162float(h));
        gAh[((size_t)(k * Nn + n)) * Nn + m] = h;
        gAl[((size_t)(k * Nn + n)) * Nn + m] = l;
    }
}

__global__ __launch_bounds__(256) void convert_x(const float* __restrict__ x)
{
    __shared__ float t[32][33];
    const int b = blockIdx.z, m0 = blockIdx.x * 32, f0 = blockIdx.y * 32;
    const int tx = threadIdx.x, ty = threadIdx.y;
    #pragma unroll
    for (int j = 0; j < 4; ++j)
        t[ty + j * 8][tx] = x[((size_t)(b * Nn + m0 + ty + j * 8)) * FT + f0 + tx];
    __syncthreads();
    #pragma unroll
    for (int j = 0; j < 4; ++j) {
        const int ft = f0 + ty + j * 8, m = m0 + tx;
        float v = t[tx][ty + j * 8];
        __nv_bfloat16 h = __float2bfloat16(v);
        __nv_bfloat16 l = __float2bfloat16(v - __bfloat162float(h));
        gXh[((size_t)b * FT + ft) * Nn + m] = h;
        gXl[((size_t)b * FT + ft) * Nn + m] = l;
    }
}

__global__ __launch_bounds__(256) void prep_wt(const float* __restrict__ w_time)
{
    int i = blockIdx.x * 256 + threadIdx.x;   // 3*64*72 = 13824
    if (i < 3 * 64 * 72) {
        int tap = i / (64 * 72), r = i - tap * (64 * 72);
        int c = r / 72, ci = r - c * 72;
        float v = (ci < 64) ? w_time[(c * 64 + ci) * 3 + tap] : 0.f;
        __nv_bfloat16 h = __float2bfloat16(v);
        __nv_bfloat16 l = __float2bfloat16(v - __bfloat162float(h));
        gWtH[i] = h;
        gWtL[i] = l;
    }
}

// ---------------------------------------------------------------------------
// mma.sync bf16-split GEMM, DOUBLE-BUFFERED: KC=32, 80B row stride.
// Row banks: 20*r mod 32 distinct over any 8 rows -> conflict-free ldmatrix.
// ---------------------------------------------------------------------------
#define KC2    32
#define RWG    80
#define A_TILE (128 * RWG)            // 10240
#define X_TILE (96 * RWG)             // 7680
#define BUFSZ  (2 * A_TILE + 2 * X_TILE)   // 35840
#define G_AH   0
#define G_AL   A_TILE
#define G_XH   (2 * A_TILE)
#define G_XL   (2 * A_TILE + X_TILE)
#define GEMM_SMEM (2 * BUFSZ)         // 71680

__global__ __launch_bounds__(256) void gemm_mma_kernel()
{
    extern __shared__ char smem[];
    const int n0 = blockIdx.x * 128;
    const int k  = blockIdx.y;
    const int b  = blockIdx.z;
    const int tid  = threadIdx.x;
    const int wid  = tid >> 5, lane = tid & 31;
    const int wm   = wid & 3;
    const int wn   = wid >> 2;
    const uint32_t smb = s2u(smem);

    const size_t aBase = ((size_t)k * Nn + n0) * Nn;
    const size_t xBase = (size_t)b * FT * Nn;

    float acc[2][6][4];
    #pragma unroll
    for (int i = 0; i < 2; ++i)
        #pragma unroll
        for (int j = 0; j < 6; ++j)
            #pragma unroll
            for (int q = 0; q < 4; ++q) acc[i][j][q] = 0.f;

    const int lrow = (lane & 7) + ((lane >> 3) & 1) * 8;
    const int lkb  = (lane >> 4) * 16;

    // load-mapping (per chunk): A 512 entries (row,seg), X 384 entries
    const int a_row = tid >> 1;                 // 2 segs per thread
    const int a_sg2 = (tid & 1) * 2;
    const int x_row0 = tid >> 1;                // first 128 rows... (96 rows x 4 segs = 384)
    // use flat loops instead for X

    auto issue = [&](int c, int buf) {
        const size_t mOff = (size_t)c * KC2;
        const uint32_t base = smb + buf * BUFSZ;
        // A: 128 rows x 4 segs; thread handles 2 segs of one row
        {
            const uint32_t d0 = base + a_row * RWG + a_sg2 * 16;
            const size_t g0 = aBase + (size_t)a_row * Nn + mOff + a_sg2 * 8;
            cp16(d0 + G_AH, gAh + g0);
            cp16(d0 + 16 + G_AH, gAh + g0 + 8);
            cp16(d0 + G_AL, gAl + g0);
            cp16(d0 + 16 + G_AL, gAl + g0 + 8);
        }
        // X: 96 rows x 4 segs = 384 entries
        for (int i = tid; i < 384; i += 256) {
            const int row = i >> 2, seg = i & 3;
            const uint32_t d = base + row * RWG + seg * 16;
            const size_t g = xBase + (size_t)row * Nn + mOff + seg * 8;
            cp16(d + G_XH, gXh + g);
            cp16(d + G_XL, gXl + g);
        }
        asm volatile("cp.async.commit_group;" ::: "memory");
    };

    const int NCH = Nn / KC2;   // 32
    issue(0, 0);

    for (int c = 0; c < NCH; ++c) {
        const int buf = c & 1;
        if (c + 1 < NCH) {
            issue(c + 1, buf ^ 1);
            asm volatile("cp.async.wait_group 1;" ::: "memory");
        } else {
            asm volatile("cp.async.wait_group 0;" ::: "memory");
        }
        __syncthreads();

        const uint32_t base = smb + buf * BUFSZ;
        #pragma unroll
        for (int ks = 0; ks < 2; ++ks) {
            const int kb = ks * 32 + lkb;
            uint32_t ah[2][4], al[2][4];
            #pragma unroll
            for (int mf = 0; mf < 2; ++mf) {
                const int r = wm * 32 + mf * 16 + lrow;
                const uint32_t off = r * RWG + kb;
                ldmx4(ah[mf], base + G_AH + off);
                ldmx4(al[mf], base + G_AL + off);
            }
            uint32_t xh[3][4], xl[3][4];
            #pragma unroll
            for (int blk = 0; blk < 3; ++blk) {
                const int r = wn * 48 + blk * 16 + lrow;
                const uint32_t off = r * RWG + kb;
                ldmx4(xh[blk], base + G_XH + off);
                ldmx4(xl[blk], base + G_XL + off);
            }
            #pragma unroll
            for (int mf = 0; mf < 2; ++mf)
                #pragma unroll
                for (int blk = 0; blk < 3; ++blk)
                    #pragma unroll
                    for (int sub = 0; sub < 2; ++sub) {
                        float* d = acc[mf][blk * 2 + sub];
                        mma16816(d, ah[mf], xh[blk][sub], xh[blk][sub + 2]);
                        mma16816(d, ah[mf], xl[blk][sub], xl[blk][sub + 2]);
                        mma16816(d, al[mf], xh[blk][sub], xh[blk][sub + 2]);
                    }
        }
        __syncthreads();
    }

    const int qrow = lane >> 2;
    const int qcol = (lane & 3) * 2;
    #pragma unroll
    for (int mf = 0; mf < 2; ++mf) {
        #pragma unroll
        for (int nf = 0; nf < 6; ++nf) {
            const int nrow = n0 + wm * 32 + mf * 16 + qrow;
            const int col  = wn * 48 + nf * 8 + qcol;
            float* base = gY + ((size_t)((b * Kk + k) * Nn) + nrow) * FT + col;
            *(float2*)(base)          = make_float2(acc[mf][nf][0], acc[mf][nf][1]);
            *(float2*)(base + 8 * FT) = make_float2(acc[mf][nf][2], acc[mf][nf][3]);
        }
    }
}

// ---------------------------------------------------------------------------
// Fused epilogue (unchanged from round 11)
// ---------------------------------------------------------------------------
#define RW    144
#define EW    0
#define EWL   27648
#define ES    55296
#define ESL   74880
#define EPO   55296
#define EXS   94464
#define EYK   97536
#define ETH   106752
#define EWR   109056
#define EBI   109824
#define EGM   110080
#define EBB   110336
#define EMU   110592
#define ERS   111104
#define ESMEM 111616
#define GRP   8
#define POW   130

__global__ __launch_bounds__(256) void fused_epi_tc(
    const float* __restrict__ x,
    const float* __restrict__ theta,
    const float* __restrict__ w_res,
    const float* __restrict__ b_time, const float* __restrict__ b_res,
    const float* __restrict__ gamma,  const float* __restrict__ beta,
    float* __restrict__ out)
{
    extern __shared__ char smem[];
    float* smf = (float*)smem;
    const uint32_t smb = s2u(smem);
    const int ng0 = blockIdx.x * GRP;
    const int b   = blockIdx.y;
    const int tid = threadIdx.x;
    const int wid = tid >> 5, lane = tid & 31;
    const int wm  = wid & 1, wn = wid >> 1;
    const int lrow = (lane & 7) + ((lane >> 3) & 1) * 8;
    const int lkb  = (lane >> 4) * 16;
    const int qrow = lane >> 2, qcol = (lane & 3) * 2;

    for (int i = tid; i < 1728; i += 256) {
        cp16(smb + EW  + i * 16, (const char*)gWtH + i * 16);
        cp16(smb + EWL + i * 16, (const char*)gWtL + i * 16);
    }
    asm volatile("cp.async.commit_group;" ::: "memory");
    for (int i = tid; i < 576; i += 256) smf[ETH/4 + i] = theta[i];
    if (tid < 192) { int c = tid / 3, f = tid - c * 3; smf[EWR/4 + f * 64 + c] = w_res[tid]; }
    if (tid < 64) {
        smf[EBI/4 + tid] = b_time[tid] + b_res[tid];
        smf[EGM/4 + tid] = gamma[tid];
        smf[EBB/4 + tid] = beta[tid];
    }
    asm volatile("cp.async.wait_group 0;" ::: "memory");
    __syncthreads();

    auto issue_prefetch = [&](int npx, int buf) {
        const int n0x = ng0 + 4 * npx;
        for (int i = tid; i < 384; i += 256) {
            if (i < 288) {
                const int h = i / 72, r = i - h * 72;
                const int k = r / 24, seg = r - k * 24;
                const uint32_t dst = smb + EYK + buf * 4608 + ((h * 3 + k) * 96 + seg * 4) * 4;
                cp16(dst, gY + ((size_t)((b * Kk + k) * Nn + n0x + h)) * FT + seg * 4);
            } else {
                const int j = i - 288;
                const int h = j / 24, seg = j - h * 24;
                const uint32_t dst = smb + EXS + buf * 1536 + (h * 96 + seg * 4) * 4;
                cp16(dst, x + ((size_t)(b * Nn + n0x + h)) * FT + seg * 4);
            }
        }
        asm volatile("cp.async.commit_group;" ::: "memory");
    };

    const int nqT  = tid >> 6;
    const int lT   = tid & 63;
    const int tTh  = lT & 31;
    const int cig  = lT >> 5;
    const int cpr  = lT >> 1;
    const int tHv  = (lT & 1) * 16;
    const int colS = tid >> 1;
    const int sS   = tid & 1;

    issue_prefetch(0, 0);

    #pragma unroll 1
    for (int np = 0; np < 2; ++np) {
        const int buf = np;
        const int n0 = ng0 + 4 * np;

        if (np == 0) {
            issue_prefetch(1, 1);
            asm volatile("cp.async.wait_group 1;" ::: "memory");
        } else {
            asm volatile("cp.async.wait_group 0;" ::: "memory");
        }

        for (int i = tid; i < 576; i += 256) {
            const int region = i / 288, r = i - region * 288;
            const int nq = r / 72, rr = (r / 36) % 2, seg = r % 36;
            char* base = smem + (region ? ESL : ES);
            *(uint32_t*)(base + (nq * 34 + (rr ? 33 : 0)) * RW + seg * 4) = 0u;
        }
        __syncthreads();

        {
            const int ci0 = cig * 32;
            float sacc[32];
            #pragma unroll
            for (int j = 0; j < 32; ++j) sacc[j] = 0.f;
            #pragma unroll
            for (int k = 0; k < Kk; ++k)
                #pragma unroll
                for (int f = 0; f < Ff; ++f) {
                    const float yv = smf[EYK/4 + buf * 1152 + (nqT * 3 + k) * 96 + f * Tt + tTh];
                    const float* tp = &smf[ETH/4 + k * (Ff * Cc) + f * Cc + ci0];
                    #pragma unroll
                    for (int j = 0; j < 32; ++j) sacc[j] += yv * tp[j];
                }
            const uint32_t rowoff = (nqT * 34 + tTh + 1) * RW + ci0 * 2;
            uint32_t* dh = (uint32_t*)(smem + ES  + rowoff);
            uint32_t* dl = (uint32_t*)(smem + ESL + rowoff);
            #pragma unroll
            for (int jj = 0; jj < 16; ++jj) {
                const float v0 = fmaxf(sacc[2 * jj],     0.f);
                const float v1 = fmaxf(sacc[2 * jj + 1], 0.f);
                const __nv_bfloat16 h0 = __float2bfloat16(v0);
                const __nv_bfloat16 h1 = __float2bfloat16(v1);
                const __nv_bfloat16 l0 = __float2bfloat16(v0 - __bfloat162float(h0));
                const __nv_bfloat16 l1 = __float2bfloat16(v1 - __bfloat162float(h1));
                dh[jj] = (uint32_t)__bfloat16_as_ushort(h0)
                       | ((uint32_t)__bfloat16_as_ushort(h1) << 16);
                dl[jj] = (uint32_t)__bfloat16_as_ushort(l0)
                       | ((uint32_t)__bfloat16_as_ushort(l1) << 16);
            }
        }
        __syncthreads();

        float acc[2][4][4];
        #pragma unroll
        for (int i = 0; i < 2; ++i)
            #pragma unroll
            for (int j = 0; j < 4; ++j)
                #pragma unroll
                for (int q = 0; q < 4; ++q) acc[i][j][q] = 0.f;

        #pragma unroll
        for (int tap = 0; tap < 3; ++tap) {
            #pragma unroll
            for (int ks = 0; ks < 4; ++ks) {
                const int kb = ks * 32 + lkb;
                uint32_t ah[2][4], al[2][4], bh[2][4], bl[2][4];
                #pragma unroll
                for (int mf = 0; mf < 2; ++mf) {
                    const uint32_t aoff = (tap * 64 + wm * 32 + mf * 16 + lrow) * RW + kb;
                    ldmx4(ah[mf], smb + EW  + aoff);
                    ldmx4(al[mf], smb + EWL + aoff);
                }
                #pragma unroll
                for (int cb = 0; cb < 2; ++cb) {
                    const uint32_t boff = (wn * 34 + cb * 16 + lrow + tap) * RW + kb;
                    ldmx4(bh[cb], smb + ES  + boff);
                    ldmx4(bl[cb], smb + ESL + boff);
                }
                #pragma unroll
                for (int mf = 0; mf < 2; ++mf)
                    #pragma unroll
                    for (int cb = 0; cb < 2; ++cb)
                        #pragma unroll
                        for (int sub = 0; sub < 2; ++sub) {
                            float* d = acc[mf][cb * 2 + sub];
                            mma16816(d, ah[mf], bh[cb][sub], bh[cb][sub + 2]);
                            mma16816(d, ah[mf], bl[cb][sub], bl[cb][sub + 2]);
                            mma16816(d, al[mf], bh[cb][sub], bh[cb][sub + 2]);
                        }
            }
        }
        __syncthreads();

        {
            float* po = smf + EPO/4;
            #pragma unroll
            for (int mf = 0; mf < 2; ++mf)
                #pragma unroll
                for (int nf = 0; nf < 4; ++nf) {
                    const int c = wm * 32 + mf * 16 + qrow;
                    const int col = wn * 32 + nf * 8 + qcol;
                    *(float2*)&po[c * POW + col]       = make_float2(acc[mf][nf][0], acc[mf][nf][1]);
                    *(float2*)&po[(c + 8) * POW + col] = make_float2(acc[mf][nf][2], acc[mf][nf][3]);
                }
        }
        __syncthreads();

        float vlo[16], vhi[16];
        {
            float* po = smf + EPO/4;
            const int clo = 2 * cpr, chi = clo + 1;
            const float wl0 = smf[EWR/4 + 0 * 64 + clo], wl1 = smf[EWR/4 + 1 * 64 + clo],
                        wl2 = smf[EWR/4 + 2 * 64 + clo];
            const float wh0 = smf[EWR/4 + 0 * 64 + chi], wh1 = smf[EWR/4 + 1 * 64 + chi],
                        wh2 = smf[EWR/4 + 2 * 64 + chi];
            const float blo = smf[EBI/4 + clo], bhi = smf[EBI/4 + chi];
            const float* xs = &smf[EXS/4 + buf * 384 + nqT * 96];
            #pragma unroll
            for (int j = 0; j < 16; ++j) {
                const int t = tHv + j, col = nqT * 32 + t;
                const float x0 = xs[t], x1 = xs[32 + t], x2 = xs[64 + t];
                vlo[j] = fmaxf(po[clo * POW + col] + blo + wl0 * x0 + wl1 * x1 + wl2 * x2, 0.f);
                vhi[j] = fmaxf(po[chi * POW + col] + bhi + wh0 * x0 + wh1 * x1 + wh2 * x2, 0.f);
                po[clo * POW + col] = vlo[j];
                po[chi * POW + col] = vhi[j];
            }
        }
        __syncthreads();

        {
            const float* po = smf + EPO/4;
            float sum = 0.f, sq = 0.f;
            #pragma unroll
            for (int q = 0; q < 32; ++q) {
                const float v = po[(sS * 32 + q) * POW + colS];
                sum += v; sq += v * v;
            }
            sum += __shfl_xor_sync(0xffffffffu, sum, 1);
            sq  += __shfl_xor_sync(0xffffffffu, sq,  1);
            if (sS == 0) {
                const float m = sum * (1.f / Ct);
                const float var = sq * (1.f / Ct) - m * m;
                smf[EMU/4 + colS] = m;
                smf[ERS/4 + colS] = rsqrtf(var + 1e-5f);
            }
        }
        __syncthreads();

        {
            const int clo = 2 * cpr, chi = clo + 1;
            const float glo = smf[EGM/4 + clo], bl = smf[EBB/4 + clo];
            const float ghi = smf[EGM/4 + chi], bh = smf[EBB/4 + chi];
            float olo[16], ohi[16];
            #pragma unroll
            for (int j = 0; j < 16; ++j) {
                const int col = nqT * 32 + tHv + j;
                const float mu = smf[EMU/4 + col];
                const float rs = smf[ERS/4 + col];
                olo[j] = (vlo[j] - mu) * rs * glo + bl;
                ohi[j] = (vhi[j] - mu) * rs * ghi + bh;
            }
            float* obase = out + ((size_t)(b * Nn + n0 + nqT)) * Ct * Tt;
            #pragma unroll
            for (int q = 0; q < 4; ++q) {
                *(float4*)(obase + clo * Tt + tHv + q * 4) =
                    make_float4(olo[q*4], olo[q*4+1], olo[q*4+2], olo[q*4+3]);
                *(float4*)(obase + chi * Tt + tHv + q * 4) =
                    make_float4(ohi[q*4], ohi[q*4+1], ohi[q*4+2], ohi[q*4+3]);
            }
        }
        __syncthreads();
    }
}

// ---------------------------------------------------------------------------
extern "C" void kernel_launch(void* const* d_in, const int* in_sizes, int n_in,
                              void* d_out, int out_size)
{
    const float* x      = (const float*)d_in[0];
    const float* cheb   = (const float*)d_in[1];
    const float* theta  = (const float*)d_in[2];
    const float* w_time = (const float*)d_in[3];
    const float* b_time = (const float*)d_in[4];
    const float* w_res  = (const float*)d_in[5];
    const float* b_res  = (const float*)d_in[6];
    const float* gamma  = (const float*)d_in[7];
    const float* beta   = (const float*)d_in[8];
    float* out = (float*)d_out;

    cudaFuncSetAttribute(gemm_mma_kernel,
                         cudaFuncAttributeMaxDynamicSharedMemorySize, GEMM_SMEM);
    cudaFuncSetAttribute(fused_epi_tc,
                         cudaFuncAttributeMaxDynamicSharedMemorySize, ESMEM);

    prep_wt<<<54, 256>>>(w_time);
    convert_cheb<<<dim3(32, 32, 3), dim3(32, 8)>>>(cheb);
    convert_x<<<dim3(32, 3, 32), dim3(32, 8)>>>(x);
    gemm_mma_kernel<<<dim3(8, 3, 32), 256, GEMM_SMEM>>>();
    fused_epi_tc<<<dim3(Nn / GRP, Bb), 256, ESMEM>>>(
        x, theta, w_res, b_time, b_res, gamma, beta, out);
}

// round 13
// speedup vs baseline: 1.1074x; 1.1074x over previous
#include <cuda_runtime.h>
#include <cuda_bf16.h>
#include <cstdint>

#define Bb 32
#define Nn 1024
#define Ff 3
#define Tt 32
#define Kk 3
#define Cc 64
#define Ct 64
#define FT (Ff*Tt)   // 96

// Scratch
__device__ float gY[(size_t)Bb * Kk * Nn * FT];            // 37.7 MB
__device__ __nv_bfloat16 gAh[(size_t)Kk * Nn * Nn];        // cheb^T hi [k][n][m]
__device__ __nv_bfloat16 gAl[(size_t)Kk * Nn * Nn];        // cheb^T lo
__device__ __nv_bfloat16 gXh[(size_t)Bb * FT * Nn];        // x^T hi [b][ft][m]
__device__ __nv_bfloat16 gXl[(size_t)Bb * FT * Nn];        // x^T lo
__device__ __align__(16) __nv_bfloat16 gWtH[3 * 64 * 72];  // W per-tap hi [tap][c][72]
__device__ __align__(16) __nv_bfloat16 gWtL[3 * 64 * 72];  // W per-tap lo

__device__ __forceinline__ uint32_t s2u(const void* p) {
    uint32_t a;
    asm("{ .reg .u64 t; cvta.to.shared.u64 t, %1; cvt.u32.u64 %0, t; }" : "=r"(a) : "l"(p));
    return a;
}
#define SWZ(o) ((o) ^ (((o) >> 3) & 0x70))

__device__ __forceinline__ void cp16(uint32_t dst, const void* src) {
    asm volatile("cp.async.cg.shared.global [%0], [%1], 16;" :: "r"(dst), "l"(src));
}
__device__ __forceinline__ void ldmx4(uint32_t* r, uint32_t addr) {
    asm volatile("ldmatrix.sync.aligned.m8n8.x4.shared.b16 {%0,%1,%2,%3}, [%4];"
                 : "=r"(r[0]), "=r"(r[1]), "=r"(r[2]), "=r"(r[3]) : "r"(addr));
}
__device__ __forceinline__ void mma16816(float* d, const uint32_t* a,
                                         uint32_t b0, uint32_t b1) {
    asm volatile(
        "mma.sync.aligned.m16n8k16.row.col.f32.bf16.bf16.f32 "
        "{%0,%1,%2,%3}, {%4,%5,%6,%7}, {%8,%9}, {%0,%1,%2,%3};"
        : "+f"(d[0]), "+f"(d[1]), "+f"(d[2]), "+f"(d[3])
        : "r"(a[0]), "r"(a[1]), "r"(a[2]), "r"(a[3]), "r"(b0), "r"(b1));
}

// ---------------------------------------------------------------------------
// Prep kernels (unchanged)
// ---------------------------------------------------------------------------
__global__ __launch_bounds__(256) void convert_cheb(const float* __restrict__ cheb)
{
    __shared__ float t[32][33];
    const int k = blockIdx.z, m0 = blockIdx.x * 32, n0 = blockIdx.y * 32;
    const int tx = threadIdx.x, ty = threadIdx.y;
    #pragma unroll
    for (int j = 0; j < 4; ++j)
        t[ty + j * 8][tx] = cheb[((size_t)(k * Nn + m0 + ty + j * 8)) * Nn + n0 + tx];
    __syncthreads();
    #pragma unroll
    for (int j = 0; j < 4; ++j) {
        const int n = n0 + ty + j * 8, m = m0 + tx;
        float v = t[tx][ty + j * 8];
        __nv_bfloat16 h = __float2bfloat16(v);
        __nv_bfloat16 l = __float2bfloat16(v - __bfloat162float(h));
        gAh[((size_t)(k * Nn + n)) * Nn + m] = h;
        gAl[((size_t)(k * Nn + n)) * Nn + m] = l;
    }
}

__global__ __launch_bounds__(256) void convert_x(const float* __restrict__ x)
{
    __shared__ float t[32][33];
    const int b = blockIdx.z, m0 = blockIdx.x * 32, f0 = blockIdx.y * 32;
    const int tx = threadIdx.x, ty = threadIdx.y;
    #pragma unroll
    for (int j = 0; j < 4; ++j)
        t[ty + j * 8][tx] = x[((size_t)(b * Nn + m0 + ty + j * 8)) * FT + f0 + tx];
    __syncthreads();
    #pragma unroll
    for (int j = 0; j < 4; ++j) {
        const int ft = f0 + ty + j * 8, m = m0 + tx;
        float v = t[tx][ty + j * 8];
        __nv_bfloat16 h = __float2bfloat16(v);
        __nv_bfloat16 l = __float2bfloat16(v - __bfloat162float(h));
        gXh[((size_t)b * FT + ft) * Nn + m] = h;
        gXl[((size_t)b * FT + ft) * Nn + m] = l;
    }
}

__global__ __launch_bounds__(256) void prep_wt(const float* __restrict__ w_time)
{
    int i = blockIdx.x * 256 + threadIdx.x;   // 3*64*72 = 13824
    if (i < 3 * 64 * 72) {
        int tap = i / (64 * 72), r = i - tap * (64 * 72);
        int c = r / 72, ci = r - c * 72;
        float v = (ci < 64) ? w_time[(c * 64 + ci) * 3 + tap] : 0.f;
        __nv_bfloat16 h = __float2bfloat16(v);
        __nv_bfloat16 l = __float2bfloat16(v - __bfloat162float(h));
        gWtH[i] = h;
        gWtL[i] = l;
    }
}

// ---------------------------------------------------------------------------
// mma.sync bf16-split GEMM (round-11 version: KC=64, serial per-chunk, 201us)
// ---------------------------------------------------------------------------
#define KC 64
#define ASZ (128 * KC * 2)
#define XSZ (96  * KC * 2)
#define SM_AH 0
#define SM_AL (SM_AH + ASZ)
#define SM_XH (SM_AL + ASZ)
#define SM_XL (SM_XH + XSZ)
#define GEMM_SMEM (SM_XL + XSZ)   // 57344

__global__ __launch_bounds__(256) void gemm_mma_kernel()
{
    extern __shared__ char smem[];
    const int n0 = blockIdx.x * 128;
    const int k  = blockIdx.y;
    const int b  = blockIdx.z;
    const int tid  = threadIdx.x;
    const int wid  = tid >> 5, lane = tid & 31;
    const int wm   = wid & 3;
    const int wn   = wid >> 2;
    const uint32_t smb = s2u(smem);

    const size_t aBase = ((size_t)k * Nn + n0) * Nn;
    const size_t xBase = (size_t)b * FT * Nn;

    float acc[2][6][4];
    #pragma unroll
    for (int i = 0; i < 2; ++i)
        #pragma unroll
        for (int j = 0; j < 6; ++j)
            #pragma unroll
            for (int q = 0; q < 4; ++q) acc[i][j][q] = 0.f;

    const int lrow = (lane & 7) + ((lane >> 3) & 1) * 8;
    const int lkb  = (lane >> 4) * 16;

    const int NCH = Nn / KC;   // 16
    for (int c = 0; c < NCH; ++c) {
        const size_t mOff = (size_t)c * KC;
        for (int i = tid; i < 1024; i += 256) {
            const int row = i >> 3, seg = i & 7;
            const uint32_t so = SWZ(row * 128 + seg * 16);
            const size_t gi = aBase + (size_t)row * Nn + mOff + seg * 8;
            cp16(smb + SM_AH + so, gAh + gi);
            cp16(smb + SM_AL + so, gAl + gi);
        }
        for (int i = tid; i < 768; i += 256) {
            const int row = i >> 3, seg = i & 7;
            const uint32_t so = SWZ(row * 128 + seg * 16);
            const size_t gi = xBase + (size_t)row * Nn + mOff + seg * 8;
            cp16(smb + SM_XH + so, gXh + gi);
            cp16(smb + SM_XL + so, gXl + gi);
        }
        asm volatile("cp.async.commit_group;" ::: "memory");
        asm volatile("cp.async.wait_group 0;" ::: "memory");
        __syncthreads();

        #pragma unroll
        for (int ks = 0; ks < 4; ++ks) {
            const int kb = ks * 32 + lkb;
            uint32_t ah[2][4], al[2][4];
            #pragma unroll
            for (int mf = 0; mf < 2; ++mf) {
                const int r = wm * 32 + mf * 16 + lrow;
                const uint32_t off = SWZ(r * 128 + kb);
                ldmx4(ah[mf], smb + SM_AH + off);
                ldmx4(al[mf], smb + SM_AL + off);
            }
            uint32_t xh[3][4], xl[3][4];
            #pragma unroll
            for (int blk = 0; blk < 3; ++blk) {
                const int r = wn * 48 + blk * 16 + lrow;
                const uint32_t off = SWZ(r * 128 + kb);
                ldmx4(xh[blk], smb + SM_XH + off);
                ldmx4(xl[blk], smb + SM_XL + off);
            }
            #pragma unroll
            for (int mf = 0; mf < 2; ++mf)
                #pragma unroll
                for (int blk = 0; blk < 3; ++blk)
                    #pragma unroll
                    for (int sub = 0; sub < 2; ++sub) {
                        float* d = acc[mf][blk * 2 + sub];
                        mma16816(d, ah[mf], xh[blk][sub], xh[blk][sub + 2]);
                        mma16816(d, ah[mf], xl[blk][sub], xl[blk][sub + 2]);
                        mma16816(d, al[mf], xh[blk][sub], xh[blk][sub + 2]);
                    }
        }
        __syncthreads();
    }

    const int qrow = lane >> 2;
    const int qcol = (lane & 3) * 2;
    #pragma unroll
    for (int mf = 0; mf < 2; ++mf) {
        #pragma unroll
        for (int nf = 0; nf < 6; ++nf) {
            const int nrow = n0 + wm * 32 + mf * 16 + qrow;
            const int col  = wn * 48 + nf * 8 + qcol;
            float* base = gY + ((size_t)((b * Kk + k) * Nn) + nrow) * FT + col;
            *(float2*)(base)          = make_float2(acc[mf][nf][0], acc[mf][nf][1]);
            *(float2*)(base + 8 * FT) = make_float2(acc[mf][nf][2], acc[mf][nf][3]);
        }
    }
}

// ---------------------------------------------------------------------------
// Fused epilogue (round-11 body), GRP=16: 4 iterations of 4 n, W-load and
// scalar setup amortized over twice the work; Y/x double-buffered prefetch.
// ---------------------------------------------------------------------------
#define RW    144
#define EW    0
#define EWL   27648
#define ES    55296
#define ESL   74880
#define EPO   55296
#define EXS   94464
#define EYK   97536
#define ETH   106752
#define EWR   109056
#define EBI   109824
#define EGM   110080
#define EBB   110336
#define EMU   110592
#define ERS   111104
#define ESMEM 111616
#define GRP   16
#define NITER (GRP / 4)
#define POW   130

__global__ __launch_bounds__(256) void fused_epi_tc(
    const float* __restrict__ x,
    const float* __restrict__ theta,
    const float* __restrict__ w_res,
    const float* __restrict__ b_time, const float* __restrict__ b_res,
    const float* __restrict__ gamma,  const float* __restrict__ beta,
    float* __restrict__ out)
{
    extern __shared__ char smem[];
    float* smf = (float*)smem;
    const uint32_t smb = s2u(smem);
    const int ng0 = blockIdx.x * GRP;
    const int b   = blockIdx.y;
    const int tid = threadIdx.x;
    const int wid = tid >> 5, lane = tid & 31;
    const int wm  = wid & 1, wn = wid >> 1;
    const int lrow = (lane & 7) + ((lane >> 3) & 1) * 8;
    const int lkb  = (lane >> 4) * 16;
    const int qrow = lane >> 2, qcol = (lane & 3) * 2;

    for (int i = tid; i < 1728; i += 256) {
        cp16(smb + EW  + i * 16, (const char*)gWtH + i * 16);
        cp16(smb + EWL + i * 16, (const char*)gWtL + i * 16);
    }
    asm volatile("cp.async.commit_group;" ::: "memory");
    for (int i = tid; i < 576; i += 256) smf[ETH/4 + i] = theta[i];
    if (tid < 192) { int c = tid / 3, f = tid - c * 3; smf[EWR/4 + f * 64 + c] = w_res[tid]; }
    if (tid < 64) {
        smf[EBI/4 + tid] = b_time[tid] + b_res[tid];
        smf[EGM/4 + tid] = gamma[tid];
        smf[EBB/4 + tid] = beta[tid];
    }
    asm volatile("cp.async.wait_group 0;" ::: "memory");
    __syncthreads();

    auto issue_prefetch = [&](int npx, int buf) {
        const int n0x = ng0 + 4 * npx;
        for (int i = tid; i < 384; i += 256) {
            if (i < 288) {
                const int h = i / 72, r = i - h * 72;
                const int k = r / 24, seg = r - k * 24;
                const uint32_t dst = smb + EYK + buf * 4608 + ((h * 3 + k) * 96 + seg * 4) * 4;
                cp16(dst, gY + ((size_t)((b * Kk + k) * Nn + n0x + h)) * FT + seg * 4);
            } else {
                const int j = i - 288;
                const int h = j / 24, seg = j - h * 24;
                const uint32_t dst = smb + EXS + buf * 1536 + (h * 96 + seg * 4) * 4;
                cp16(dst, x + ((size_t)(b * Nn + n0x + h)) * FT + seg * 4);
            }
        }
        asm volatile("cp.async.commit_group;" ::: "memory");
    };

    const int nqT  = tid >> 6;
    const int lT   = tid & 63;
    const int tTh  = lT & 31;
    const int cig  = lT >> 5;
    const int cpr  = lT >> 1;
    const int tHv  = (lT & 1) * 16;
    const int colS = tid >> 1;
    const int sS   = tid & 1;

    issue_prefetch(0, 0);

    #pragma unroll 1
    for (int np = 0; np < NITER; ++np) {
        const int buf = np & 1;
        const int n0 = ng0 + 4 * np;

        if (np + 1 < NITER) {
            issue_prefetch(np + 1, buf ^ 1);
            asm volatile("cp.async.wait_group 1;" ::: "memory");
        } else {
            asm volatile("cp.async.wait_group 0;" ::: "memory");
        }

        for (int i = tid; i < 576; i += 256) {
            const int region = i / 288, r = i - region * 288;
            const int nq = r / 72, rr = (r / 36) % 2, seg = r % 36;
            char* base = smem + (region ? ESL : ES);
            *(uint32_t*)(base + (nq * 34 + (rr ? 33 : 0)) * RW + seg * 4) = 0u;
        }
        __syncthreads();

        {
            const int ci0 = cig * 32;
            float sacc[32];
            #pragma unroll
            for (int j = 0; j < 32; ++j) sacc[j] = 0.f;
            #pragma unroll
            for (int k = 0; k < Kk; ++k)
                #pragma unroll
                for (int f = 0; f < Ff; ++f) {
                    const float yv = smf[EYK/4 + buf * 1152 + (nqT * 3 + k) * 96 + f * Tt + tTh];
                    const float* tp = &smf[ETH/4 + k * (Ff * Cc) + f * Cc + ci0];
                    #pragma unroll
                    for (int j = 0; j < 32; ++j) sacc[j] += yv * tp[j];
                }
            const uint32_t rowoff = (nqT * 34 + tTh + 1) * RW + ci0 * 2;
            uint32_t* dh = (uint32_t*)(smem + ES  + rowoff);
            uint32_t* dl = (uint32_t*)(smem + ESL + rowoff);
            #pragma unroll
            for (int jj = 0; jj < 16; ++jj) {
                const float v0 = fmaxf(sacc[2 * jj],     0.f);
                const float v1 = fmaxf(sacc[2 * jj + 1], 0.f);
                const __nv_bfloat16 h0 = __float2bfloat16(v0);
                const __nv_bfloat16 h1 = __float2bfloat16(v1);
                const __nv_bfloat16 l0 = __float2bfloat16(v0 - __bfloat162float(h0));
                const __nv_bfloat16 l1 = __float2bfloat16(v1 - __bfloat162float(h1));
                dh[jj] = (uint32_t)__bfloat16_as_ushort(h0)
                       | ((uint32_t)__bfloat16_as_ushort(h1) << 16);
                dl[jj] = (uint32_t)__bfloat16_as_ushort(l0)
                       | ((uint32_t)__bfloat16_as_ushort(l1) << 16);
            }
        }
        __syncthreads();

        float acc[2][4][4];
        #pragma unroll
        for (int i = 0; i < 2; ++i)
            #pragma unroll
            for (int j = 0; j < 4; ++j)
                #pragma unroll
                for (int q = 0; q < 4; ++q) acc[i][j][q] = 0.f;

        #pragma unroll
        for (int tap = 0; tap < 3; ++tap) {
            #pragma unroll
            for (int ks = 0; ks < 4; ++ks) {
                const int kb = ks * 32 + lkb;
                uint32_t ah[2][4], al[2][4], bh[2][4], bl[2][4];
                #pragma unroll
                for (int mf = 0; mf < 2; ++mf) {
                    const uint32_t aoff = (tap * 64 + wm * 32 + mf * 16 + lrow) * RW + kb;
                    ldmx4(ah[mf], smb + EW  + aoff);
                    ldmx4(al[mf], smb + EWL + aoff);
                }
                #pragma unroll
                for (int cb = 0; cb < 2; ++cb) {
                    const uint32_t boff = (wn * 34 + cb * 16 + lrow + tap) * RW + kb;
                    ldmx4(bh[cb], smb + ES  + boff);
                    ldmx4(bl[cb], smb + ESL + boff);
                }
                #pragma unroll
                for (int mf = 0; mf < 2; ++mf)
                    #pragma unroll
                    for (int cb = 0; cb < 2; ++cb)
                        #pragma unroll
                        for (int sub = 0; sub < 2; ++sub) {
                            float* d = acc[mf][cb * 2 + sub];
                            mma16816(d, ah[mf], bh[cb][sub], bh[cb][sub + 2]);
                            mma16816(d, ah[mf], bl[cb][sub], bl[cb][sub + 2]);
                            mma16816(d, al[mf], bh[cb][sub], bh[cb][sub + 2]);
                        }
            }
        }
        __syncthreads();

        {
            float* po = smf + EPO/4;
            #pragma unroll
            for (int mf = 0; mf < 2; ++mf)
                #pragma unroll
                for (int nf = 0; nf < 4; ++nf) {
                    const int c = wm * 32 + mf * 16 + qrow;
                    const int col = wn * 32 + nf * 8 + qcol;
                    *(float2*)&po[c * POW + col]       = make_float2(acc[mf][nf][0], acc[mf][nf][1]);
                    *(float2*)&po[(c + 8) * POW + col] = make_float2(acc[mf][nf][2], acc[mf][nf][3]);
                }
        }
        __syncthreads();

        float vlo[16], vhi[16];
        {
            float* po = smf + EPO/4;
            const int clo = 2 * cpr, chi = clo + 1;
            const float wl0 = smf[EWR/4 + 0 * 64 + clo], wl1 = smf[EWR/4 + 1 * 64 + clo],
                        wl2 = smf[EWR/4 + 2 * 64 + clo];
            const float wh0 = smf[EWR/4 + 0 * 64 + chi], wh1 = smf[EWR/4 + 1 * 64 + chi],
                        wh2 = smf[EWR/4 + 2 * 64 + chi];
            const float blo = smf[EBI/4 + clo], bhi = smf[EBI/4 + chi];
            const float* xs = &smf[EXS/4 + buf * 384 + nqT * 96];
            #pragma unroll
            for (int j = 0; j < 16; ++j) {
                const int t = tHv + j, col = nqT * 32 + t;
                const float x0 = xs[t], x1 = xs[32 + t], x2 = xs[64 + t];
                vlo[j] = fmaxf(po[clo * POW + col] + blo + wl0 * x0 + wl1 * x1 + wl2 * x2, 0.f);
                vhi[j] = fmaxf(po[chi * POW + col] + bhi + wh0 * x0 + wh1 * x1 + wh2 * x2, 0.f);
                po[clo * POW + col] = vlo[j];
                po[chi * POW + col] = vhi[j];
            }
        }
        __syncthreads();

        {
            const float* po = smf + EPO/4;
            float sum = 0.f, sq = 0.f;
            #pragma unroll
            for (int q = 0; q < 32; ++q) {
                const float v = po[(sS * 32 + q) * POW + colS];
                sum += v; sq += v * v;
            }
            sum += __shfl_xor_sync(0xffffffffu, sum, 1);
            sq  += __shfl_xor_sync(0xffffffffu, sq,  1);
            if (sS == 0) {
                const float m = sum * (1.f / Ct);
                const float var = sq * (1.f / Ct) - m * m;
                smf[EMU/4 + colS] = m;
                smf[ERS/4 + colS] = rsqrtf(var + 1e-5f);
            }
        }
        __syncthreads();

        {
            const int clo = 2 * cpr, chi = clo + 1;
            const float glo = smf[EGM/4 + clo], bl = smf[EBB/4 + clo];
            const float ghi = smf[EGM/4 + chi], bh = smf[EBB/4 + chi];
            float olo[16], ohi[16];
            #pragma unroll
            for (int j = 0; j < 16; ++j) {
                const int col = nqT * 32 + tHv + j;
                const float mu = smf[EMU/4 + col];
                const float rs = smf[ERS/4 + col];
                olo[j] = (vlo[j] - mu) * rs * glo + bl;
                ohi[j] = (vhi[j] - mu) * rs * ghi + bh;
            }
            float* obase = out + ((size_t)(b * Nn + n0 + nqT)) * Ct * Tt;
            #pragma unroll
            for (int q = 0; q < 4; ++q) {
                *(float4*)(obase + clo * Tt + tHv + q * 4) =
                    make_float4(olo[q*4], olo[q*4+1], olo[q*4+2], olo[q*4+3]);
                *(float4*)(obase + chi * Tt + tHv + q * 4) =
                    make_float4(ohi[q*4], ohi[q*4+1], ohi[q*4+2], ohi[q*4+3]);
            }
        }
        __syncthreads();
    }
}

// ---------------------------------------------------------------------------
extern "C" void kernel_launch(void* const* d_in, const int* in_sizes, int n_in,
                              void* d_out, int out_size)
{
    const float* x      = (const float*)d_in[0];
    const float* cheb   = (const float*)d_in[1];
    const float* theta  = (const float*)d_in[2];
    const float* w_time = (const float*)d_in[3];
    const float* b_time = (const float*)d_in[4];
    const float* w_res  = (const float*)d_in[5];
    const float* b_res  = (const float*)d_in[6];
    const float* gamma  = (const float*)d_in[7];
    const float* beta   = (const float*)d_in[8];
    float* out = (float*)d_out;

    cudaFuncSetAttribute(gemm_mma_kernel,
                         cudaFuncAttributeMaxDynamicSharedMemorySize, GEMM_SMEM);
    cudaFuncSetAttribute(fused_epi_tc,
                         cudaFuncAttributeMaxDynamicSharedMemorySize, ESMEM);

    prep_wt<<<54, 256>>>(w_time);
    convert_cheb<<<dim3(32, 32, 3), dim3(32, 8)>>>(cheb);
    convert_x<<<dim3(32, 3, 32), dim3(32, 8)>>>(x);
    gemm_mma_kernel<<<dim3(8, 3, 32), 256, GEMM_SMEM>>>();
    fused_epi_tc<<<dim3(Nn / GRP, Bb), 256, ESMEM>>>(
        x, theta, w_res, b_time, b_res, gamma, beta, out);
}

// round 14
// speedup vs baseline: 1.1397x; 1.0292x over previous
#include <cuda_runtime.h>
#include <cuda_bf16.h>
#include <cstdint>

#define Bb 32
#define Nn 1024
#define Ff 3
#define Tt 32
#define Kk 3
#define Cc 64
#define Ct 64
#define FT (Ff*Tt)   // 96

// Scratch
__device__ float gY[(size_t)Bb * Kk * Nn * FT];            // 37.7 MB
__device__ __nv_bfloat16 gAh[(size_t)Kk * Nn * Nn];        // cheb^T hi [k][n][m]
__device__ __nv_bfloat16 gAl[(size_t)Kk * Nn * Nn];        // cheb^T lo
__device__ __nv_bfloat16 gXh[(size_t)Bb * FT * Nn];        // x^T hi [b][ft][m]
__device__ __nv_bfloat16 gXl[(size_t)Bb * FT * Nn];        // x^T lo
__device__ __align__(16) __nv_bfloat16 gWtH[3 * 64 * 72];  // W per-tap hi [tap][c][72]
__device__ __align__(16) __nv_bfloat16 gWtL[3 * 64 * 72];  // W per-tap lo

__device__ __forceinline__ uint32_t s2u(const void* p) {
    uint32_t a;
    asm("{ .reg .u64 t; cvta.to.shared.u64 t, %1; cvt.u32.u64 %0, t; }" : "=r"(a) : "l"(p));
    return a;
}
#define SWZ(o) ((o) ^ (((o) >> 3) & 0x70))

__device__ __forceinline__ void cp16(uint32_t dst, const void* src) {
    asm volatile("cp.async.cg.shared.global [%0], [%1], 16;" :: "r"(dst), "l"(src));
}
__device__ __forceinline__ void ldmx4(uint32_t* r, uint32_t addr) {
    asm volatile("ldmatrix.sync.aligned.m8n8.x4.shared.b16 {%0,%1,%2,%3}, [%4];"
                 : "=r"(r[0]), "=r"(r[1]), "=r"(r[2]), "=r"(r[3]) : "r"(addr));
}
__device__ __forceinline__ void mma16816(float* d, const uint32_t* a,
                                         uint32_t b0, uint32_t b1) {
    asm volatile(
        "mma.sync.aligned.m16n8k16.row.col.f32.bf16.bf16.f32 "
        "{%0,%1,%2,%3}, {%4,%5,%6,%7}, {%8,%9}, {%0,%1,%2,%3};"
        : "+f"(d[0]), "+f"(d[1]), "+f"(d[2]), "+f"(d[3])
        : "r"(a[0]), "r"(a[1]), "r"(a[2]), "r"(a[3]), "r"(b0), "r"(b1));
}

// ---------------------------------------------------------------------------
// Prep kernels (unchanged)
// ---------------------------------------------------------------------------
__global__ __launch_bounds__(256) void convert_cheb(const float* __restrict__ cheb)
{
    __shared__ float t[32][33];
    const int k = blockIdx.z, m0 = blockIdx.x * 32, n0 = blockIdx.y * 32;
    const int tx = threadIdx.x, ty = threadIdx.y;
    #pragma unroll
    for (int j = 0; j < 4; ++j)
        t[ty + j * 8][tx] = cheb[((size_t)(k * Nn + m0 + ty + j * 8)) * Nn + n0 + tx];
    __syncthreads();
    #pragma unroll
    for (int j = 0; j < 4; ++j) {
        const int n = n0 + ty + j * 8, m = m0 + tx;
        float v = t[tx][ty + j * 8];
        __nv_bfloat16 h = __float2bfloat16(v);
        __nv_bfloat16 l = __float2bfloat16(v - __bfloat162float(h));
        gAh[((size_t)(k * Nn + n)) * Nn + m] = h;
        gAl[((size_t)(k * Nn + n)) * Nn + m] = l;
    }
}

__global__ __launch_bounds__(256) void convert_x(const float* __restrict__ x)
{
    __shared__ float t[32][33];
    const int b = blockIdx.z, m0 = blockIdx.x * 32, f0 = blockIdx.y * 32;
    const int tx = threadIdx.x, ty = threadIdx.y;
    #pragma unroll
    for (int j = 0; j < 4; ++j)
        t[ty + j * 8][tx] = x[((size_t)(b * Nn + m0 + ty + j * 8)) * FT + f0 + tx];
    __syncthreads();
    #pragma unroll
    for (int j = 0; j < 4; ++j) {
        const int ft = f0 + ty + j * 8, m = m0 + tx;
        float v = t[tx][ty + j * 8];
        __nv_bfloat16 h = __float2bfloat16(v);
        __nv_bfloat16 l = __float2bfloat16(v - __bfloat162float(h));
        gXh[((size_t)b * FT + ft) * Nn + m] = h;
        gXl[((size_t)b * FT + ft) * Nn + m] = l;
    }
}

__global__ __launch_bounds__(256) void prep_wt(const float* __restrict__ w_time)
{
    int i = blockIdx.x * 256 + threadIdx.x;   // 3*64*72 = 13824
    if (i < 3 * 64 * 72) {
        int tap = i / (64 * 72), r = i - tap * (64 * 72);
        int c = r / 72, ci = r - c * 72;
        float v = (ci < 64) ? w_time[(c * 64 + ci) * 3 + tap] : 0.f;
        __nv_bfloat16 h = __float2bfloat16(v);
        __nv_bfloat16 l = __float2bfloat16(v - __bfloat162float(h));
        gWtH[i] = h;
        gWtL[i] = l;
    }
}

// ---------------------------------------------------------------------------
// mma.sync bf16-split GEMM: 128-thread CTAs, tile 64n x 96ft, KC=64.
// 4 warps (2 m x 2 n), warp tile 32x48 (same inner loop as before).
// 40 KB smem -> 4 CTAs/SM for deeper load/mma interleave across CTAs.
// grid (16, 3, 32)
// ---------------------------------------------------------------------------
#define KC 64
#define ASZ (64 * KC * 2)             // 8192 per A half
#define XSZ (96 * KC * 2)             // 12288 per X half
#define SM_AH 0
#define SM_AL (SM_AH + ASZ)
#define SM_XH (SM_AL + ASZ)
#define SM_XL (SM_XH + XSZ)
#define GEMM_SMEM (SM_XL + XSZ)       // 40960

__global__ __launch_bounds__(128) void gemm_mma_kernel()
{
    extern __shared__ char smem[];
    const int n0 = blockIdx.x * 64;
    const int k  = blockIdx.y;
    const int b  = blockIdx.z;
    const int tid  = threadIdx.x;
    const int wid  = tid >> 5, lane = tid & 31;
    const int wm   = wid & 1;         // 2 m-warps (32 rows each)
    const int wn   = wid >> 1;        // 2 n-warps (48 cols each)
    const uint32_t smb = s2u(smem);

    const size_t aBase = ((size_t)k * Nn + n0) * Nn;
    const size_t xBase = (size_t)b * FT * Nn;

    float acc[2][6][4];
    #pragma unroll
    for (int i = 0; i < 2; ++i)
        #pragma unroll
        for (int j = 0; j < 6; ++j)
            #pragma unroll
            for (int q = 0; q < 4; ++q) acc[i][j][q] = 0.f;

    const int lrow = (lane & 7) + ((lane >> 3) & 1) * 8;
    const int lkb  = (lane >> 4) * 16;

    const int NCH = Nn / KC;   // 16
    for (int c = 0; c < NCH; ++c) {
        const size_t mOff = (size_t)c * KC;
        // A: 64 rows x 8 segs = 512 entries
        for (int i = tid; i < 512; i += 128) {
            const int row = i >> 3, seg = i & 7;
            const uint32_t so = SWZ(row * 128 + seg * 16);
            const size_t gi = aBase + (size_t)row * Nn + mOff + seg * 8;
            cp16(smb + SM_AH + so, gAh + gi);
            cp16(smb + SM_AL + so, gAl + gi);
        }
        // X: 96 rows x 8 segs = 768 entries
        for (int i = tid; i < 768; i += 128) {
            const int row = i >> 3, seg = i & 7;
            const uint32_t so = SWZ(row * 128 + seg * 16);
            const size_t gi = xBase + (size_t)row * Nn + mOff + seg * 8;
            cp16(smb + SM_XH + so, gXh + gi);
            cp16(smb + SM_XL + so, gXl + gi);
        }
        asm volatile("cp.async.commit_group;" ::: "memory");
        asm volatile("cp.async.wait_group 0;" ::: "memory");
        __syncthreads();

        #pragma unroll
        for (int ks = 0; ks < 4; ++ks) {
            const int kb = ks * 32 + lkb;
            uint32_t ah[2][4], al[2][4];
            #pragma unroll
            for (int mf = 0; mf < 2; ++mf) {
                const int r = wm * 32 + mf * 16 + lrow;
                const uint32_t off = SWZ(r * 128 + kb);
                ldmx4(ah[mf], smb + SM_AH + off);
                ldmx4(al[mf], smb + SM_AL + off);
            }
            uint32_t xh[3][4], xl[3][4];
            #pragma unroll
            for (int blk = 0; blk < 3; ++blk) {
                const int r = wn * 48 + blk * 16 + lrow;
                const uint32_t off = SWZ(r * 128 + kb);
                ldmx4(xh[blk], smb + SM_XH + off);
                ldmx4(xl[blk], smb + SM_XL + off);
            }
            #pragma unroll
            for (int mf = 0; mf < 2; ++mf)
                #pragma unroll
                for (int blk = 0; blk < 3; ++blk)
                    #pragma unroll
                    for (int sub = 0; sub < 2; ++sub) {
                        float* d = acc[mf][blk * 2 + sub];
                        mma16816(d, ah[mf], xh[blk][sub], xh[blk][sub + 2]);
                        mma16816(d, ah[mf], xl[blk][sub], xl[blk][sub + 2]);
                        mma16816(d, al[mf], xh[blk][sub], xh[blk][sub + 2]);
                    }
        }
        __syncthreads();
    }

    const int qrow = lane >> 2;
    const int qcol = (lane & 3) * 2;
    #pragma unroll
    for (int mf = 0; mf < 2; ++mf) {
        #pragma unroll
        for (int nf = 0; nf < 6; ++nf) {
            const int nrow = n0 + wm * 32 + mf * 16 + qrow;
            const int col  = wn * 48 + nf * 8 + qcol;
            float* base = gY + ((size_t)((b * Kk + k) * Nn) + nrow) * FT + col;
            *(float2*)(base)          = make_float2(acc[mf][nf][0], acc[mf][nf][1]);
            *(float2*)(base + 8 * FT) = make_float2(acc[mf][nf][2], acc[mf][nf][3]);
        }
    }
}

// ---------------------------------------------------------------------------
// Fused epilogue (unchanged from round 13: GRP=16, tap-shifted conv)
// ---------------------------------------------------------------------------
#define RW    144
#define EW    0
#define EWL   27648
#define ES    55296
#define ESL   74880
#define EPO   55296
#define EXS   94464
#define EYK   97536
#define ETH   106752
#define EWR   109056
#define EBI   109824
#define EGM   110080
#define EBB   110336
#define EMU   110592
#define ERS   111104
#define ESMEM 111616
#define GRP   16
#define NITER (GRP / 4)
#define POW   130

__global__ __launch_bounds__(256) void fused_epi_tc(
    const float* __restrict__ x,
    const float* __restrict__ theta,
    const float* __restrict__ w_res,
    const float* __restrict__ b_time, const float* __restrict__ b_res,
    const float* __restrict__ gamma,  const float* __restrict__ beta,
    float* __restrict__ out)
{
    extern __shared__ char smem[];
    float* smf = (float*)smem;
    const uint32_t smb = s2u(smem);
    const int ng0 = blockIdx.x * GRP;
    const int b   = blockIdx.y;
    const int tid = threadIdx.x;
    const int wid = tid >> 5, lane = tid & 31;
    const int wm  = wid & 1, wn = wid >> 1;
    const int lrow = (lane & 7) + ((lane >> 3) & 1) * 8;
    const int lkb  = (lane >> 4) * 16;
    const int qrow = lane >> 2, qcol = (lane & 3) * 2;

    for (int i = tid; i < 1728; i += 256) {
        cp16(smb + EW  + i * 16, (const char*)gWtH + i * 16);
        cp16(smb + EWL + i * 16, (const char*)gWtL + i * 16);
    }
    asm volatile("cp.async.commit_group;" ::: "memory");
    for (int i = tid; i < 576; i += 256) smf[ETH/4 + i] = theta[i];
    if (tid < 192) { int c = tid / 3, f = tid - c * 3; smf[EWR/4 + f * 64 + c] = w_res[tid]; }
    if (tid < 64) {
        smf[EBI/4 + tid] = b_time[tid] + b_res[tid];
        smf[EGM/4 + tid] = gamma[tid];
        smf[EBB/4 + tid] = beta[tid];
    }
    asm volatile("cp.async.wait_group 0;" ::: "memory");
    __syncthreads();

    auto issue_prefetch = [&](int npx, int buf) {
        const int n0x = ng0 + 4 * npx;
        for (int i = tid; i < 384; i += 256) {
            if (i < 288) {
                const int h = i / 72, r = i - h * 72;
                const int k = r / 24, seg = r - k * 24;
                const uint32_t dst = smb + EYK + buf * 4608 + ((h * 3 + k) * 96 + seg * 4) * 4;
                cp16(dst, gY + ((size_t)((b * Kk + k) * Nn + n0x + h)) * FT + seg * 4);
            } else {
                const int j = i - 288;
                const int h = j / 24, seg = j - h * 24;
                const uint32_t dst = smb + EXS + buf * 1536 + (h * 96 + seg * 4) * 4;
                cp16(dst, x + ((size_t)(b * Nn + n0x + h)) * FT + seg * 4);
            }
        }
        asm volatile("cp.async.commit_group;" ::: "memory");
    };

    const int nqT  = tid >> 6;
    const int lT   = tid & 63;
    const int tTh  = lT & 31;
    const int cig  = lT >> 5;
    const int cpr  = lT >> 1;
    const int tHv  = (lT & 1) * 16;
    const int colS = tid >> 1;
    const int sS   = tid & 1;

    issue_prefetch(0, 0);

    #pragma unroll 1
    for (int np = 0; np < NITER; ++np) {
        const int buf = np & 1;
        const int n0 = ng0 + 4 * np;

        if (np + 1 < NITER) {
            issue_prefetch(np + 1, buf ^ 1);
            asm volatile("cp.async.wait_group 1;" ::: "memory");
        } else {
            asm volatile("cp.async.wait_group 0;" ::: "memory");
        }

        for (int i = tid; i < 576; i += 256) {
            const int region = i / 288, r = i - region * 288;
            const int nq = r / 72, rr = (r / 36) % 2, seg = r % 36;
            char* base = smem + (region ? ESL : ES);
            *(uint32_t*)(base + (nq * 34 + (rr ? 33 : 0)) * RW + seg * 4) = 0u;
        }
        __syncthreads();

        {
            const int ci0 = cig * 32;
            float sacc[32];
            #pragma unroll
            for (int j = 0; j < 32; ++j) sacc[j] = 0.f;
            #pragma unroll
            for (int k = 0; k < Kk; ++k)
                #pragma unroll
                for (int f = 0; f < Ff; ++f) {
                    const float yv = smf[EYK/4 + buf * 1152 + (nqT * 3 + k) * 96 + f * Tt + tTh];
                    const float* tp = &smf[ETH/4 + k * (Ff * Cc) + f * Cc + ci0];
                    #pragma unroll
                    for (int j = 0; j < 32; ++j) sacc[j] += yv * tp[j];
                }
            const uint32_t rowoff = (nqT * 34 + tTh + 1) * RW + ci0 * 2;
            uint32_t* dh = (uint32_t*)(smem + ES  + rowoff);
            uint32_t* dl = (uint32_t*)(smem + ESL + rowoff);
            #pragma unroll
            for (int jj = 0; jj < 16; ++jj) {
                const float v0 = fmaxf(sacc[2 * jj],     0.f);
                const float v1 = fmaxf(sacc[2 * jj + 1], 0.f);
                const __nv_bfloat16 h0 = __float2bfloat16(v0);
                const __nv_bfloat16 h1 = __float2bfloat16(v1);
                const __nv_bfloat16 l0 = __float2bfloat16(v0 - __bfloat162float(h0));
                const __nv_bfloat16 l1 = __float2bfloat16(v1 - __bfloat162float(h1));
                dh[jj] = (uint32_t)__bfloat16_as_ushort(h0)
                       | ((uint32_t)__bfloat16_as_ushort(h1) << 16);
                dl[jj] = (uint32_t)__bfloat16_as_ushort(l0)
                       | ((uint32_t)__bfloat16_as_ushort(l1) << 16);
            }
        }
        __syncthreads();

        float acc[2][4][4];
        #pragma unroll
        for (int i = 0; i < 2; ++i)
            #pragma unroll
            for (int j = 0; j < 4; ++j)
                #pragma unroll
                for (int q = 0; q < 4; ++q) acc[i][j][q] = 0.f;

        #pragma unroll
        for (int tap = 0; tap < 3; ++tap) {
            #pragma unroll
            for (int ks = 0; ks < 4; ++ks) {
                const int kb = ks * 32 + lkb;
                uint32_t ah[2][4], al[2][4], bh[2][4], bl[2][4];
                #pragma unroll
                for (int mf = 0; mf < 2; ++mf) {
                    const uint32_t aoff = (tap * 64 + wm * 32 + mf * 16 + lrow) * RW + kb;
                    ldmx4(ah[mf], smb + EW  + aoff);
                    ldmx4(al[mf], smb + EWL + aoff);
                }
                #pragma unroll
                for (int cb = 0; cb < 2; ++cb) {
                    const uint32_t boff = (wn * 34 + cb * 16 + lrow + tap) * RW + kb;
                    ldmx4(bh[cb], smb + ES  + boff);
                    ldmx4(bl[cb], smb + ESL + boff);
                }
                #pragma unroll
                for (int mf = 0; mf < 2; ++mf)
                    #pragma unroll
                    for (int cb = 0; cb < 2; ++cb)
                        #pragma unroll
                        for (int sub = 0; sub < 2; ++sub) {
                            float* d = acc[mf][cb * 2 + sub];
                            mma16816(d, ah[mf], bh[cb][sub], bh[cb][sub + 2]);
                            mma16816(d, ah[mf], bl[cb][sub], bl[cb][sub + 2]);
                            mma16816(d, al[mf], bh[cb][sub], bh[cb][sub + 2]);
                        }
            }
        }
        __syncthreads();

        {
            float* po = smf + EPO/4;
            #pragma unroll
            for (int mf = 0; mf < 2; ++mf)
                #pragma unroll
                for (int nf = 0; nf < 4; ++nf) {
                    const int c = wm * 32 + mf * 16 + qrow;
                    const int col = wn * 32 + nf * 8 + qcol;
                    *(float2*)&po[c * POW + col]       = make_float2(acc[mf][nf][0], acc[mf][nf][1]);
                    *(float2*)&po[(c + 8) * POW + col] = make_float2(acc[mf][nf][2], acc[mf][nf][3]);
                }
        }
        __syncthreads();

        float vlo[16], vhi[16];
        {
            float* po = smf + EPO/4;
            const int clo = 2 * cpr, chi = clo + 1;
            const float wl0 = smf[EWR/4 + 0 * 64 + clo], wl1 = smf[EWR/4 + 1 * 64 + clo],
                        wl2 = smf[EWR/4 + 2 * 64 + clo];
            const float wh0 = smf[EWR/4 + 0 * 64 + chi], wh1 = smf[EWR/4 + 1 * 64 + chi],
                        wh2 = smf[EWR/4 + 2 * 64 + chi];
            const float blo = smf[EBI/4 + clo], bhi = smf[EBI/4 + chi];
            const float* xs = &smf[EXS/4 + buf * 384 + nqT * 96];
            #pragma unroll
            for (int j = 0; j < 16; ++j) {
                const int t = tHv + j, col = nqT * 32 + t;
                const float x0 = xs[t], x1 = xs[32 + t], x2 = xs[64 + t];
                vlo[j] = fmaxf(po[clo * POW + col] + blo + wl0 * x0 + wl1 * x1 + wl2 * x2, 0.f);
                vhi[j] = fmaxf(po[chi * POW + col] + bhi + wh0 * x0 + wh1 * x1 + wh2 * x2, 0.f);
                po[clo * POW + col] = vlo[j];
                po[chi * POW + col] = vhi[j];
            }
        }
        __syncthreads();

        {
            const float* po = smf + EPO/4;
            float sum = 0.f, sq = 0.f;
            #pragma unroll
            for (int q = 0; q < 32; ++q) {
                const float v = po[(sS * 32 + q) * POW + colS];
                sum += v; sq += v * v;
            }
            sum += __shfl_xor_sync(0xffffffffu, sum, 1);
            sq  += __shfl_xor_sync(0xffffffffu, sq,  1);
            if (sS == 0) {
                const float m = sum * (1.f / Ct);
                const float var = sq * (1.f / Ct) - m * m;
                smf[EMU/4 + colS] = m;
                smf[ERS/4 + colS] = rsqrtf(var + 1e-5f);
            }
        }
        __syncthreads();

        {
            const int clo = 2 * cpr, chi = clo + 1;
            const float glo = smf[EGM/4 + clo], bl = smf[EBB/4 + clo];
            const float ghi = smf[EGM/4 + chi], bh = smf[EBB/4 + chi];
            float olo[16], ohi[16];
            #pragma unroll
            for (int j = 0; j < 16; ++j) {
                const int col = nqT * 32 + tHv + j;
                const float mu = smf[EMU/4 + col];
                const float rs = smf[ERS/4 + col];
                olo[j] = (vlo[j] - mu) * rs * glo + bl;
                ohi[j] = (vhi[j] - mu) * rs * ghi + bh;
            }
            float* obase = out + ((size_t)(b * Nn + n0 + nqT)) * Ct * Tt;
            #pragma unroll
            for (int q = 0; q < 4; ++q) {
                *(float4*)(obase + clo * Tt + tHv + q * 4) =
                    make_float4(olo[q*4], olo[q*4+1], olo[q*4+2], olo[q*4+3]);
                *(float4*)(obase + chi * Tt + tHv + q * 4) =
                    make_float4(ohi[q*4], ohi[q*4+1], ohi[q*4+2], ohi[q*4+3]);
            }
        }
        __syncthreads();
    }
}

// ---------------------------------------------------------------------------
extern "C" void kernel_launch(void* const* d_in, const int* in_sizes, int n_in,
                              void* d_out, int out_size)
{
    const float* x      = (const float*)d_in[0];
    const float* cheb   = (const float*)d_in[1];
    const float* theta  = (const float*)d_in[2];
    const float* w_time = (const float*)d_in[3];
    const float* b_time = (const float*)d_in[4];
    const float* w_res  = (const float*)d_in[5];
    const float* b_res  = (const float*)d_in[6];
    const float* gamma  = (const float*)d_in[7];
    const float* beta   = (const float*)d_in[8];
    float* out = (float*)d_out;

    cudaFuncSetAttribute(gemm_mma_kernel,
                         cudaFuncAttributeMaxDynamicSharedMemorySize, GEMM_SMEM);
    cudaFuncSetAttribute(fused_epi_tc,
                         cudaFuncAttributeMaxDynamicSharedMemorySize, ESMEM);

    prep_wt<<<54, 256>>>(w_time);
    convert_cheb<<<dim3(32, 32, 3), dim3(32, 8)>>>(cheb);
    convert_x<<<dim3(32, 3, 32), dim3(32, 8)>>>(x);
    gemm_mma_kernel<<<dim3(16, 3, 32), 128, GEMM_SMEM>>>();
    fused_epi_tc<<<dim3(Nn / GRP, Bb), 256, ESMEM>>>(
        x, theta, w_res, b_time, b_res, gamma, beta, out);
}

// round 15
// speedup vs baseline: 1.1678x; 1.0247x over previous
#include <cuda_runtime.h>
#include <cuda_bf16.h>
#include <cstdint>

#define Bb 32
#define Nn 1024
#define Ff 3
#define Tt 32
#define Kk 3
#define Cc 64
#define Ct 64
#define FT (Ff*Tt)   // 96

// Scratch
__device__ float gY[(size_t)Bb * Kk * Nn * FT];            // 37.7 MB
__device__ __nv_bfloat16 gAh[(size_t)Kk * Nn * Nn];
__device__ __nv_bfloat16 gAl[(size_t)Kk * Nn * Nn];
__device__ __nv_bfloat16 gXh[(size_t)Bb * FT * Nn];
__device__ __nv_bfloat16 gXl[(size_t)Bb * FT * Nn];
__device__ __align__(16) __nv_bfloat16 gWtH[3 * 64 * 72];
__device__ __align__(16) __nv_bfloat16 gWtL[3 * 64 * 72];

__device__ __forceinline__ uint32_t s2u(const void* p) {
    uint32_t a;
    asm("{ .reg .u64 t; cvta.to.shared.u64 t, %1; cvt.u32.u64 %0, t; }" : "=r"(a) : "l"(p));
    return a;
}
#define SWZ(o) ((o) ^ (((o) >> 3) & 0x70))

__device__ __forceinline__ void cp16(uint32_t dst, const void* src) {
    asm volatile("cp.async.cg.shared.global [%0], [%1], 16;" :: "r"(dst), "l"(src));
}
__device__ __forceinline__ void ldmx4(uint32_t* r, uint32_t addr) {
    asm volatile("ldmatrix.sync.aligned.m8n8.x4.shared.b16 {%0,%1,%2,%3}, [%4];"
                 : "=r"(r[0]), "=r"(r[1]), "=r"(r[2]), "=r"(r[3]) : "r"(addr));
}
__device__ __forceinline__ void mma16816(float* d, const uint32_t* a,
                                         uint32_t b0, uint32_t b1) {
    asm volatile(
        "mma.sync.aligned.m16n8k16.row.col.f32.bf16.bf16.f32 "
        "{%0,%1,%2,%3}, {%4,%5,%6,%7}, {%8,%9}, {%0,%1,%2,%3};"
        : "+f"(d[0]), "+f"(d[1]), "+f"(d[2]), "+f"(d[3])
        : "r"(a[0]), "r"(a[1]), "r"(a[2]), "r"(a[3]), "r"(b0), "r"(b1));
}

// ---------------------------------------------------------------------------
// Merged prep kernel: blocks [0,3072) cheb, [3072,6144) x, [6144,6198) w_time.
// ---------------------------------------------------------------------------
__global__ __launch_bounds__(256) void prep_all(
    const float* __restrict__ cheb, const float* __restrict__ x,
    const float* __restrict__ w_time)
{
    __shared__ float t[32][33];
    const int bid = blockIdx.x;
    const int tid = threadIdx.x;
    const int tx = tid & 31, ty = tid >> 5;

    if (bid < 3072) {
        const int k = bid >> 10, r = bid & 1023;
        const int m0 = (r >> 5) * 32, n0 = (r & 31) * 32;
        #pragma unroll
        for (int j = 0; j < 4; ++j)
            t[ty + j * 8][tx] = cheb[((size_t)(k * Nn + m0 + ty + j * 8)) * Nn + n0 + tx];
        __syncthreads();
        #pragma unroll
        for (int j = 0; j < 4; ++j) {
            const int n = n0 + ty + j * 8, m = m0 + tx;
            float v = t[tx][ty + j * 8];
            __nv_bfloat16 h = __float2bfloat16(v);
            __nv_bfloat16 l = __float2bfloat16(v - __bfloat162float(h));
            gAh[((size_t)(k * Nn + n)) * Nn + m] = h;
            gAl[((size_t)(k * Nn + n)) * Nn + m] = l;
        }
    } else if (bid < 6144) {
        const int r = bid - 3072;
        const int b = r / 96, r2 = r - b * 96;
        const int m0 = (r2 / 3) * 32, f0 = (r2 % 3) * 32;
        #pragma unroll
        for (int j = 0; j < 4; ++j)
            t[ty + j * 8][tx] = x[((size_t)(b * Nn + m0 + ty + j * 8)) * FT + f0 + tx];
        __syncthreads();
        #pragma unroll
        for (int j = 0; j < 4; ++j) {
            const int ft = f0 + ty + j * 8, m = m0 + tx;
            float v = t[tx][ty + j * 8];
            __nv_bfloat16 h = __float2bfloat16(v);
            __nv_bfloat16 l = __float2bfloat16(v - __bfloat162float(h));
            gXh[((size_t)b * FT + ft) * Nn + m] = h;
            gXl[((size_t)b * FT + ft) * Nn + m] = l;
        }
    } else {
        const int i = (bid - 6144) * 256 + tid;   // 3*64*72 = 13824
        if (i < 3 * 64 * 72) {
            int tap = i / (64 * 72), r = i - tap * (64 * 72);
            int c = r / 72, ci = r - c * 72;
            float v = (ci < 64) ? w_time[(c * 64 + ci) * 3 + tap] : 0.f;
            __nv_bfloat16 h = __float2bfloat16(v);
            __nv_bfloat16 l = __float2bfloat16(v - __bfloat162float(h));
            gWtH[i] = h;
            gWtL[i] = l;
        }
    }
}

// ---------------------------------------------------------------------------
// mma.sync bf16-split GEMM: 128-thread CTAs, tile 64n x 96ft, KC=64,
// DOUBLE-BUFFERED (80 KB, 2 CTAs/SM): chunk c+1 cp.async issued before
// waiting on chunk c.
// ---------------------------------------------------------------------------
#define KC 64
#define ASZ (64 * KC * 2)             // 8192 per A half
#define XSZ (96 * KC * 2)             // 12288 per X half
#define SM_AH 0
#define SM_AL ASZ
#define SM_XH (2 * ASZ)
#define SM_XL (2 * ASZ + XSZ)
#define BUFB  (2 * ASZ + 2 * XSZ)     // 40960
#define GEMM_SMEM (2 * BUFB)          // 81920

__global__ __launch_bounds__(128) void gemm_mma_kernel()
{
    extern __shared__ char smem[];
    const int n0 = blockIdx.x * 64;
    const int k  = blockIdx.y;
    const int b  = blockIdx.z;
    const int tid  = threadIdx.x;
    const int wid  = tid >> 5, lane = tid & 31;
    const int wm   = wid & 1;
    const int wn   = wid >> 1;
    const uint32_t smb = s2u(smem);

    const size_t aBase = ((size_t)k * Nn + n0) * Nn;
    const size_t xBase = (size_t)b * FT * Nn;

    float acc[2][6][4];
    #pragma unroll
    for (int i = 0; i < 2; ++i)
        #pragma unroll
        for (int j = 0; j < 6; ++j)
            #pragma unroll
            for (int q = 0; q < 4; ++q) acc[i][j][q] = 0.f;

    const int lrow = (lane & 7) + ((lane >> 3) & 1) * 8;
    const int lkb  = (lane >> 4) * 16;

    auto issue = [&](int c, int buf) {
        const size_t mOff = (size_t)c * KC;
        const uint32_t base = smb + buf * BUFB;
        for (int i = tid; i < 512; i += 128) {
            const int row = i >> 3, seg = i & 7;
            const uint32_t so = SWZ(row * 128 + seg * 16);
            const size_t gi = aBase + (size_t)row * Nn + mOff + seg * 8;
            cp16(base + SM_AH + so, gAh + gi);
            cp16(base + SM_AL + so, gAl + gi);
        }
        for (int i = tid; i < 768; i += 128) {
            const int row = i >> 3, seg = i & 7;
            const uint32_t so = SWZ(row * 128 + seg * 16);
            const size_t gi = xBase + (size_t)row * Nn + mOff + seg * 8;
            cp16(base + SM_XH + so, gXh + gi);
            cp16(base + SM_XL + so, gXl + gi);
        }
        asm volatile("cp.async.commit_group;" ::: "memory");
    };

    const int NCH = Nn / KC;   // 16
    issue(0, 0);
    for (int c = 0; c < NCH; ++c) {
        const int buf = c & 1;
        if (c + 1 < NCH) {
            issue(c + 1, buf ^ 1);
            asm volatile("cp.async.wait_group 1;" ::: "memory");
        } else {
            asm volatile("cp.async.wait_group 0;" ::: "memory");
        }
        __syncthreads();

        const uint32_t base = smb + buf * BUFB;
        #pragma unroll
        for (int ks = 0; ks < 4; ++ks) {
            const int kb = ks * 32 + lkb;
            uint32_t ah[2][4], al[2][4];
            #pragma unroll
            for (int mf = 0; mf < 2; ++mf) {
                const int r = wm * 32 + mf * 16 + lrow;
                const uint32_t off = SWZ(r * 128 + kb);
                ldmx4(ah[mf], base + SM_AH + off);
                ldmx4(al[mf], base + SM_AL + off);
            }
            uint32_t xh[3][4], xl[3][4];
            #pragma unroll
            for (int blk = 0; blk < 3; ++blk) {
                const int r = wn * 48 + blk * 16 + lrow;
                const uint32_t off = SWZ(r * 128 + kb);
                ldmx4(xh[blk], base + SM_XH + off);
                ldmx4(xl[blk], base + SM_XL + off);
            }
            #pragma unroll
            for (int mf = 0; mf < 2; ++mf)
                #pragma unroll
                for (int blk = 0; blk < 3; ++blk)
                    #pragma unroll
                    for (int sub = 0; sub < 2; ++sub) {
                        float* d = acc[mf][blk * 2 + sub];
                        mma16816(d, ah[mf], xh[blk][sub], xh[blk][sub + 2]);
                        mma16816(d, ah[mf], xl[blk][sub], xl[blk][sub + 2]);
                        mma16816(d, al[mf], xh[blk][sub], xh[blk][sub + 2]);
                    }
        }
        __syncthreads();   // all reads of buf done before it is refilled
    }

    const int qrow = lane >> 2;
    const int qcol = (lane & 3) * 2;
    #pragma unroll
    for (int mf = 0; mf < 2; ++mf) {
        #pragma unroll
        for (int nf = 0; nf < 6; ++nf) {
            const int nrow = n0 + wm * 32 + mf * 16 + qrow;
            const int col  = wn * 48 + nf * 8 + qcol;
            float* base = gY + ((size_t)((b * Kk + k) * Nn) + nrow) * FT + col;
            *(float2*)(base)          = make_float2(acc[mf][nf][0], acc[mf][nf][1]);
            *(float2*)(base + 8 * FT) = make_float2(acc[mf][nf][2], acc[mf][nf][3]);
        }
    }
}

// ---------------------------------------------------------------------------
// Fused epilogue: GRP=16, tap-shifted conv; residual+bias+relu FUSED into the
// conv register epilogue (6 syncs/iter, normalize reads po from smem).
// ---------------------------------------------------------------------------
#define RW    144
#define EW    0
#define EWL   27648
#define ES    55296
#define ESL   74880
#define EPO   55296
#define EXS   94464
#define EYK   97536
#define ETH   106752
#define EWR   109056
#define EBI   109824
#define EGM   110080
#define EBB   110336
#define EMU   110592
#define ERS   111104
#define ESMEM 111616
#define GRP   16
#define NITER (GRP / 4)
#define POW   130

__global__ __launch_bounds__(256) void fused_epi_tc(
    const float* __restrict__ x,
    const float* __restrict__ theta,
    const float* __restrict__ w_res,
    const float* __restrict__ b_time, const float* __restrict__ b_res,
    const float* __restrict__ gamma,  const float* __restrict__ beta,
    float* __restrict__ out)
{
    extern __shared__ char smem[];
    float* smf = (float*)smem;
    const uint32_t smb = s2u(smem);
    const int ng0 = blockIdx.x * GRP;
    const int b   = blockIdx.y;
    const int tid = threadIdx.x;
    const int wid = tid >> 5, lane = tid & 31;
    const int wm  = wid & 1, wn = wid >> 1;
    const int lrow = (lane & 7) + ((lane >> 3) & 1) * 8;
    const int lkb  = (lane >> 4) * 16;
    const int qrow = lane >> 2, qcol = (lane & 3) * 2;

    for (int i = tid; i < 1728; i += 256) {
        cp16(smb + EW  + i * 16, (const char*)gWtH + i * 16);
        cp16(smb + EWL + i * 16, (const char*)gWtL + i * 16);
    }
    asm volatile("cp.async.commit_group;" ::: "memory");
    for (int i = tid; i < 576; i += 256) smf[ETH/4 + i] = theta[i];
    if (tid < 192) { int c = tid / 3, f = tid - c * 3; smf[EWR/4 + f * 64 + c] = w_res[tid]; }
    if (tid < 64) {
        smf[EBI/4 + tid] = b_time[tid] + b_res[tid];
        smf[EGM/4 + tid] = gamma[tid];
        smf[EBB/4 + tid] = beta[tid];
    }
    asm volatile("cp.async.wait_group 0;" ::: "memory");
    __syncthreads();

    auto issue_prefetch = [&](int npx, int buf) {
        const int n0x = ng0 + 4 * npx;
        for (int i = tid; i < 384; i += 256) {
            if (i < 288) {
                const int h = i / 72, r = i - h * 72;
                const int k = r / 24, seg = r - k * 24;
                const uint32_t dst = smb + EYK + buf * 4608 + ((h * 3 + k) * 96 + seg * 4) * 4;
                cp16(dst, gY + ((size_t)((b * Kk + k) * Nn + n0x + h)) * FT + seg * 4);
            } else {
                const int j = i - 288;
                const int h = j / 24, seg = j - h * 24;
                const uint32_t dst = smb + EXS + buf * 1536 + (h * 96 + seg * 4) * 4;
                cp16(dst, x + ((size_t)(b * Nn + n0x + h)) * FT + seg * 4);
            }
        }
        asm volatile("cp.async.commit_group;" ::: "memory");
    };

    const int nqT  = tid >> 6;
    const int lT   = tid & 63;
    const int tTh  = lT & 31;
    const int cig  = lT >> 5;
    const int cpr  = lT >> 1;
    const int tHv  = (lT & 1) * 16;
    const int colS = tid >> 1;
    const int sS   = tid & 1;

    issue_prefetch(0, 0);

    #pragma unroll 1
    for (int np = 0; np < NITER; ++np) {
        const int buf = np & 1;
        const int n0 = ng0 + 4 * np;

        if (np + 1 < NITER) {
            issue_prefetch(np + 1, buf ^ 1);
            asm volatile("cp.async.wait_group 1;" ::: "memory");
        } else {
            asm volatile("cp.async.wait_group 0;" ::: "memory");
        }

        for (int i = tid; i < 576; i += 256) {
            const int region = i / 288, r = i - region * 288;
            const int nq = r / 72, rr = (r / 36) % 2, seg = r % 36;
            char* base = smem + (region ? ESL : ES);
            *(uint32_t*)(base + (nq * 34 + (rr ? 33 : 0)) * RW + seg * 4) = 0u;
        }
        __syncthreads();

        // ---- theta + relu + split -> S ----
        {
            const int ci0 = cig * 32;
            float sacc[32];
            #pragma unroll
            for (int j = 0; j < 32; ++j) sacc[j] = 0.f;
            #pragma unroll
            for (int k = 0; k < Kk; ++k)
                #pragma unroll
                for (int f = 0; f < Ff; ++f) {
                    const float yv = smf[EYK/4 + buf * 1152 + (nqT * 3 + k) * 96 + f * Tt + tTh];
                    const float* tp = &smf[ETH/4 + k * (Ff * Cc) + f * Cc + ci0];
                    #pragma unroll
                    for (int j = 0; j < 32; ++j) sacc[j] += yv * tp[j];
                }
            const uint32_t rowoff = (nqT * 34 + tTh + 1) * RW + ci0 * 2;
            uint32_t* dh = (uint32_t*)(smem + ES  + rowoff);
            uint32_t* dl = (uint32_t*)(smem + ESL + rowoff);
            #pragma unroll
            for (int jj = 0; jj < 16; ++jj) {
                const float v0 = fmaxf(sacc[2 * jj],     0.f);
                const float v1 = fmaxf(sacc[2 * jj + 1], 0.f);
                const __nv_bfloat16 h0 = __float2bfloat16(v0);
                const __nv_bfloat16 h1 = __float2bfloat16(v1);
                const __nv_bfloat16 l0 = __float2bfloat16(v0 - __bfloat162float(h0));
                const __nv_bfloat16 l1 = __float2bfloat16(v1 - __bfloat162float(h1));
                dh[jj] = (uint32_t)__bfloat16_as_ushort(h0)
                       | ((uint32_t)__bfloat16_as_ushort(h1) << 16);
                dl[jj] = (uint32_t)__bfloat16_as_ushort(l0)
                       | ((uint32_t)__bfloat16_as_ushort(l1) << 16);
            }
        }
        __syncthreads();

        // ---- conv GEMM ----
        float acc[2][4][4];
        #pragma unroll
        for (int i = 0; i < 2; ++i)
            #pragma unroll
            for (int j = 0; j < 4; ++j)
                #pragma unroll
                for (int q = 0; q < 4; ++q) acc[i][j][q] = 0.f;

        #pragma unroll
        for (int tap = 0; tap < 3; ++tap) {
            #pragma unroll
            for (int ks = 0; ks < 4; ++ks) {
                const int kb = ks * 32 + lkb;
                uint32_t ah[2][4], al[2][4], bh[2][4], bl[2][4];
                #pragma unroll
                for (int mf = 0; mf < 2; ++mf) {
                    const uint32_t aoff = (tap * 64 + wm * 32 + mf * 16 + lrow) * RW + kb;
                    ldmx4(ah[mf], smb + EW  + aoff);
                    ldmx4(al[mf], smb + EWL + aoff);
                }
                #pragma unroll
                for (int cb = 0; cb < 2; ++cb) {
                    const uint32_t boff = (wn * 34 + cb * 16 + lrow + tap) * RW + kb;
                    ldmx4(bh[cb], smb + ES  + boff);
                    ldmx4(bl[cb], smb + ESL + boff);
                }
                #pragma unroll
                for (int mf = 0; mf < 2; ++mf)
                    #pragma unroll
                    for (int cb = 0; cb < 2; ++cb)
                        #pragma unroll
                        for (int sub = 0; sub < 2; ++sub) {
                            float* d = acc[mf][cb * 2 + sub];
                            mma16816(d, ah[mf], bh[cb][sub], bh[cb][sub + 2]);
                            mma16816(d, ah[mf], bl[cb][sub], bl[cb][sub + 2]);
                            mma16816(d, al[mf], bh[cb][sub], bh[cb][sub + 2]);
                        }
            }
        }
        __syncthreads();   // all S reads done -> safe to overlay po

        // ---- fused: bias + residual + relu in registers, write po ----
        {
            float* po = smf + EPO/4;
            const float* xs = &smf[EXS/4 + buf * 384 + wn * 96];
            #pragma unroll
            for (int mf = 0; mf < 2; ++mf) {
                #pragma unroll
                for (int rr = 0; rr < 2; ++rr) {
                    const int c = wm * 32 + mf * 16 + qrow + rr * 8;
                    const float w0 = smf[EWR/4 + 0 * 64 + c];
                    const float w1 = smf[EWR/4 + 1 * 64 + c];
                    const float w2 = smf[EWR/4 + 2 * 64 + c];
                    const float bi = smf[EBI/4 + c];
                    #pragma unroll
                    for (int nf = 0; nf < 4; ++nf) {
                        const int t0 = nf * 8 + qcol;
                        float v0 = acc[mf][nf][rr * 2 + 0] + bi
                                 + w0 * xs[t0] + w1 * xs[32 + t0] + w2 * xs[64 + t0];
                        float v1 = acc[mf][nf][rr * 2 + 1] + bi
                                 + w0 * xs[t0 + 1] + w1 * xs[32 + t0 + 1] + w2 * xs[64 + t0 + 1];
                        *(float2*)&po[c * POW + wn * 32 + t0] =
                            make_float2(fmaxf(v0, 0.f), fmaxf(v1, 0.f));
                    }
                }
            }
        }
        __syncthreads();

        // ---- LN stats ----
        {
            const float* po = smf + EPO/4;
            float sum = 0.f, sq = 0.f;
            #pragma unroll
            for (int q = 0; q < 32; ++q) {
                const float v = po[(sS * 32 + q) * POW + colS];
                sum += v; sq += v * v;
            }
            sum += __shfl_xor_sync(0xffffffffu, sum, 1);
            sq  += __shfl_xor_sync(0xffffffffu, sq,  1);
            if (sS == 0) {
                const float m = sum * (1.f / Ct);
                const float var = sq * (1.f / Ct) - m * m;
                smf[EMU/4 + colS] = m;
                smf[ERS/4 + colS] = rsqrtf(var + 1e-5f);
            }
        }
        __syncthreads();

        // ---- normalize (read po) + store ----
        {
            const float* po = smf + EPO/4;
            const int clo = 2 * cpr, chi = clo + 1;
            const float glo = smf[EGM/4 + clo], bl = smf[EBB/4 + clo];
            const float ghi = smf[EGM/4 + chi], bh = smf[EBB/4 + chi];
            float olo[16], ohi[16];
            #pragma unroll
            for (int j = 0; j < 16; ++j) {
                const int col = nqT * 32 + tHv + j;
                const float mu = smf[EMU/4 + col];
                const float rs = smf[ERS/4 + col];
                olo[j] = (po[clo * POW + col] - mu) * rs * glo + bl;
                ohi[j] = (po[chi * POW + col] - mu) * rs * ghi + bh;
            }
            float* obase = out + ((size_t)(b * Nn + n0 + nqT)) * Ct * Tt;
            #pragma unroll
            for (int q = 0; q < 4; ++q) {
                *(float4*)(obase + clo * Tt + tHv + q * 4) =
                    make_float4(olo[q*4], olo[q*4+1], olo[q*4+2], olo[q*4+3]);
                *(float4*)(obase + chi * Tt + tHv + q * 4) =
                    make_float4(ohi[q*4], ohi[q*4+1], ohi[q*4+2], ohi[q*4+3]);
            }
        }
        __syncthreads();
    }
}

// ---------------------------------------------------------------------------
extern "C" void kernel_launch(void* const* d_in, const int* in_sizes, int n_in,
                              void* d_out, int out_size)
{
    const float* x      = (const float*)d_in[0];
    const float* cheb   = (const float*)d_in[1];
    const float* theta  = (const float*)d_in[2];
    const float* w_time = (const float*)d_in[3];
    const float* b_time = (const float*)d_in[4];
    const float* w_res  = (const float*)d_in[5];
    const float* b_res  = (const float*)d_in[6];
    const float* gamma  = (const float*)d_in[7];
    const float* beta   = (const float*)d_in[8];
    float* out = (float*)d_out;

    cudaFuncSetAttribute(gemm_mma_kernel,
                         cudaFuncAttributeMaxDynamicSharedMemorySize, GEMM_SMEM);
    cudaFuncSetAttribute(fused_epi_tc,
                         cudaFuncAttributeMaxDynamicSharedMemorySize, ESMEM);

    prep_all<<<6198, 256>>>(cheb, x, w_time);
    gemm_mma_kernel<<<dim3(16, 3, 32), 128, GEMM_SMEM>>>();
    fused_epi_tc<<<dim3(Nn / GRP, Bb), 256, ESMEM>>>(
        x, theta, w_res, b_time, b_res, gamma, beta, out);
}

// round 16
// speedup vs baseline: 1.1962x; 1.0243x over previous
#include <cuda_runtime.h>
#include <cuda_bf16.h>
#include <cstdint>

#define Bb 32
#define Nn 1024
#define Ff 3
#define Tt 32
#define Kk 3
#define Cc 64
#define Ct 64
#define FT (Ff*Tt)   // 96

// Scratch
__device__ float gY[(size_t)Bb * Kk * Nn * FT];            // 37.7 MB
__device__ __nv_bfloat16 gAh[(size_t)Kk * Nn * Nn];
__device__ __nv_bfloat16 gAl[(size_t)Kk * Nn * Nn];
__device__ __nv_bfloat16 gXh[(size_t)Bb * FT * Nn];
__device__ __nv_bfloat16 gXl[(size_t)Bb * FT * Nn];
__device__ __align__(16) __nv_bfloat16 gWtH[3 * 64 * 72];
__device__ __align__(16) __nv_bfloat16 gWtL[3 * 64 * 72];

__device__ __forceinline__ uint32_t s2u(const void* p) {
    uint32_t a;
    asm("{ .reg .u64 t; cvta.to.shared.u64 t, %1; cvt.u32.u64 %0, t; }" : "=r"(a) : "l"(p));
    return a;
}
#define SWZ(o) ((o) ^ (((o) >> 3) & 0x70))

__device__ __forceinline__ void cp16(uint32_t dst, const void* src) {
    asm volatile("cp.async.cg.shared.global [%0], [%1], 16;" :: "r"(dst), "l"(src));
}
__device__ __forceinline__ void ldmx4(uint32_t* r, uint32_t addr) {
    asm volatile("ldmatrix.sync.aligned.m8n8.x4.shared.b16 {%0,%1,%2,%3}, [%4];"
                 : "=r"(r[0]), "=r"(r[1]), "=r"(r[2]), "=r"(r[3]) : "r"(addr));
}
__device__ __forceinline__ void mma16816(float* d, const uint32_t* a,
                                         uint32_t b0, uint32_t b1) {
    asm volatile(
        "mma.sync.aligned.m16n8k16.row.col.f32.bf16.bf16.f32 "
        "{%0,%1,%2,%3}, {%4,%5,%6,%7}, {%8,%9}, {%0,%1,%2,%3};"
        : "+f"(d[0]), "+f"(d[1]), "+f"(d[2]), "+f"(d[3])
        : "r"(a[0]), "r"(a[1]), "r"(a[2]), "r"(a[3]), "r"(b0), "r"(b1));
}

// ---------------------------------------------------------------------------
// Merged prep kernel: blocks [0,3072) cheb, [3072,6144) x, [6144,6198) w_time.
// ---------------------------------------------------------------------------
__global__ __launch_bounds__(256) void prep_all(
    const float* __restrict__ cheb, const float* __restrict__ x,
    const float* __restrict__ w_time)
{
    __shared__ float t[32][33];
    const int bid = blockIdx.x;
    const int tid = threadIdx.x;
    const int tx = tid & 31, ty = tid >> 5;

    if (bid < 3072) {
        const int k = bid >> 10, r = bid & 1023;
        const int m0 = (r >> 5) * 32, n0 = (r & 31) * 32;
        #pragma unroll
        for (int j = 0; j < 4; ++j)
            t[ty + j * 8][tx] = cheb[((size_t)(k * Nn + m0 + ty + j * 8)) * Nn + n0 + tx];
        __syncthreads();
        #pragma unroll
        for (int j = 0; j < 4; ++j) {
            const int n = n0 + ty + j * 8, m = m0 + tx;
            float v = t[tx][ty + j * 8];
            __nv_bfloat16 h = __float2bfloat16(v);
            __nv_bfloat16 l = __float2bfloat16(v - __bfloat162float(h));
            gAh[((size_t)(k * Nn + n)) * Nn + m] = h;
            gAl[((size_t)(k * Nn + n)) * Nn + m] = l;
        }
    } else if (bid < 6144) {
        const int r = bid - 3072;
        const int b = r / 96, r2 = r - b * 96;
        const int m0 = (r2 / 3) * 32, f0 = (r2 % 3) * 32;
        #pragma unroll
        for (int j = 0; j < 4; ++j)
            t[ty + j * 8][tx] = x[((size_t)(b * Nn + m0 + ty + j * 8)) * FT + f0 + tx];
        __syncthreads();
        #pragma unroll
        for (int j = 0; j < 4; ++j) {
            const int ft = f0 + ty + j * 8, m = m0 + tx;
            float v = t[tx][ty + j * 8];
            __nv_bfloat16 h = __float2bfloat16(v);
            __nv_bfloat16 l = __float2bfloat16(v - __bfloat162float(h));
            gXh[((size_t)b * FT + ft) * Nn + m] = h;
            gXl[((size_t)b * FT + ft) * Nn + m] = l;
        }
    } else {
        const int i = (bid - 6144) * 256 + tid;   // 3*64*72 = 13824
        if (i < 3 * 64 * 72) {
            int tap = i / (64 * 72), r = i - tap * (64 * 72);
            int c = r / 72, ci = r - c * 72;
            float v = (ci < 64) ? w_time[(c * 64 + ci) * 3 + tap] : 0.f;
            __nv_bfloat16 h = __float2bfloat16(v);
            __nv_bfloat16 l = __float2bfloat16(v - __bfloat162float(h));
            gWtH[i] = h;
            gWtL[i] = l;
        }
    }
}

// ---------------------------------------------------------------------------
// mma.sync bf16-split GEMM (round-14 version, measured 186us):
// 128-thread CTAs, tile 64n x 96ft, KC=64, single buffer, 4 CTAs/SM.
// ---------------------------------------------------------------------------
#define KC 64
#define ASZ (64 * KC * 2)             // 8192 per A half
#define XSZ (96 * KC * 2)             // 12288 per X half
#define SM_AH 0
#define SM_AL (SM_AH + ASZ)
#define SM_XH (SM_AL + ASZ)
#define SM_XL (SM_XH + XSZ)
#define GEMM_SMEM (SM_XL + XSZ)       // 40960

__global__ __launch_bounds__(128) void gemm_mma_kernel()
{
    extern __shared__ char smem[];
    const int n0 = blockIdx.x * 64;
    const int k  = blockIdx.y;
    const int b  = blockIdx.z;
    const int tid  = threadIdx.x;
    const int wid  = tid >> 5, lane = tid & 31;
    const int wm   = wid & 1;
    const int wn   = wid >> 1;
    const uint32_t smb = s2u(smem);

    const size_t aBase = ((size_t)k * Nn + n0) * Nn;
    const size_t xBase = (size_t)b * FT * Nn;

    float acc[2][6][4];
    #pragma unroll
    for (int i = 0; i < 2; ++i)
        #pragma unroll
        for (int j = 0; j < 6; ++j)
            #pragma unroll
            for (int q = 0; q < 4; ++q) acc[i][j][q] = 0.f;

    const int lrow = (lane & 7) + ((lane >> 3) & 1) * 8;
    const int lkb  = (lane >> 4) * 16;

    const int NCH = Nn / KC;   // 16
    for (int c = 0; c < NCH; ++c) {
        const size_t mOff = (size_t)c * KC;
        for (int i = tid; i < 512; i += 128) {
            const int row = i >> 3, seg = i & 7;
            const uint32_t so = SWZ(row * 128 + seg * 16);
            const size_t gi = aBase + (size_t)row * Nn + mOff + seg * 8;
            cp16(smb + SM_AH + so, gAh + gi);
            cp16(smb + SM_AL + so, gAl + gi);
        }
        for (int i = tid; i < 768; i += 128) {
            const int row = i >> 3, seg = i & 7;
            const uint32_t so = SWZ(row * 128 + seg * 16);
            const size_t gi = xBase + (size_t)row * Nn + mOff + seg * 8;
            cp16(smb + SM_XH + so, gXh + gi);
            cp16(smb + SM_XL + so, gXl + gi);
        }
        asm volatile("cp.async.commit_group;" ::: "memory");
        asm volatile("cp.async.wait_group 0;" ::: "memory");
        __syncthreads();

        #pragma unroll
        for (int ks = 0; ks < 4; ++ks) {
            const int kb = ks * 32 + lkb;
            uint32_t ah[2][4], al[2][4];
            #pragma unroll
            for (int mf = 0; mf < 2; ++mf) {
                const int r = wm * 32 + mf * 16 + lrow;
                const uint32_t off = SWZ(r * 128 + kb);
                ldmx4(ah[mf], smb + SM_AH + off);
                ldmx4(al[mf], smb + SM_AL + off);
            }
            uint32_t xh[3][4], xl[3][4];
            #pragma unroll
            for (int blk = 0; blk < 3; ++blk) {
                const int r = wn * 48 + blk * 16 + lrow;
                const uint32_t off = SWZ(r * 128 + kb);
                ldmx4(xh[blk], smb + SM_XH + off);
                ldmx4(xl[blk], smb + SM_XL + off);
            }
            #pragma unroll
            for (int mf = 0; mf < 2; ++mf)
                #pragma unroll
                for (int blk = 0; blk < 3; ++blk)
                    #pragma unroll
                    for (int sub = 0; sub < 2; ++sub) {
                        float* d = acc[mf][blk * 2 + sub];
                        mma16816(d, ah[mf], xh[blk][sub], xh[blk][sub + 2]);
                        mma16816(d, ah[mf], xl[blk][sub], xl[blk][sub + 2]);
                        mma16816(d, al[mf], xh[blk][sub], xh[blk][sub + 2]);
                    }
        }
        __syncthreads();
    }

    const int qrow = lane >> 2;
    const int qcol = (lane & 3) * 2;
    #pragma unroll
    for (int mf = 0; mf < 2; ++mf) {
        #pragma unroll
        for (int nf = 0; nf < 6; ++nf) {
            const int nrow = n0 + wm * 32 + mf * 16 + qrow;
            const int col  = wn * 48 + nf * 8 + qcol;
            float* base = gY + ((size_t)((b * Kk + k) * Nn) + nrow) * FT + col;
            *(float2*)(base)          = make_float2(acc[mf][nf][0], acc[mf][nf][1]);
            *(float2*)(base + 8 * FT) = make_float2(acc[mf][nf][2], acc[mf][nf][3]);
        }
    }
}

// ---------------------------------------------------------------------------
// Fused epilogue (round-15 version: GRP=16, fused residual in conv epilogue)
// ---------------------------------------------------------------------------
#define RW    144
#define EW    0
#define EWL   27648
#define ES    55296
#define ESL   74880
#define EPO   55296
#define EXS   94464
#define EYK   97536
#define ETH   106752
#define EWR   109056
#define EBI   109824
#define EGM   110080
#define EBB   110336
#define EMU   110592
#define ERS   111104
#define ESMEM 111616
#define GRP   16
#define NITER (GRP / 4)
#define POW   130

__global__ __launch_bounds__(256) void fused_epi_tc(
    const float* __restrict__ x,
    const float* __restrict__ theta,
    const float* __restrict__ w_res,
    const float* __restrict__ b_time, const float* __restrict__ b_res,
    const float* __restrict__ gamma,  const float* __restrict__ beta,
    float* __restrict__ out)
{
    extern __shared__ char smem[];
    float* smf = (float*)smem;
    const uint32_t smb = s2u(smem);
    const int ng0 = blockIdx.x * GRP;
    const int b   = blockIdx.y;
    const int tid = threadIdx.x;
    const int wid = tid >> 5, lane = tid & 31;
    const int wm  = wid & 1, wn = wid >> 1;
    const int lrow = (lane & 7) + ((lane >> 3) & 1) * 8;
    const int lkb  = (lane >> 4) * 16;
    const int qrow = lane >> 2, qcol = (lane & 3) * 2;

    for (int i = tid; i < 1728; i += 256) {
        cp16(smb + EW  + i * 16, (const char*)gWtH + i * 16);
        cp16(smb + EWL + i * 16, (const char*)gWtL + i * 16);
    }
    asm volatile("cp.async.commit_group;" ::: "memory");
    for (int i = tid; i < 576; i += 256) smf[ETH/4 + i] = theta[i];
    if (tid < 192) { int c = tid / 3, f = tid - c * 3; smf[EWR/4 + f * 64 + c] = w_res[tid]; }
    if (tid < 64) {
        smf[EBI/4 + tid] = b_time[tid] + b_res[tid];
        smf[EGM/4 + tid] = gamma[tid];
        smf[EBB/4 + tid] = beta[tid];
    }
    asm volatile("cp.async.wait_group 0;" ::: "memory");
    __syncthreads();

    auto issue_prefetch = [&](int npx, int buf) {
        const int n0x = ng0 + 4 * npx;
        for (int i = tid; i < 384; i += 256) {
            if (i < 288) {
                const int h = i / 72, r = i - h * 72;
                const int k = r / 24, seg = r - k * 24;
                const uint32_t dst = smb + EYK + buf * 4608 + ((h * 3 + k) * 96 + seg * 4) * 4;
                cp16(dst, gY + ((size_t)((b * Kk + k) * Nn + n0x + h)) * FT + seg * 4);
            } else {
                const int j = i - 288;
                const int h = j / 24, seg = j - h * 24;
                const uint32_t dst = smb + EXS + buf * 1536 + (h * 96 + seg * 4) * 4;
                cp16(dst, x + ((size_t)(b * Nn + n0x + h)) * FT + seg * 4);
            }
        }
        asm volatile("cp.async.commit_group;" ::: "memory");
    };

    const int nqT  = tid >> 6;
    const int lT   = tid & 63;
    const int tTh  = lT & 31;
    const int cig  = lT >> 5;
    const int cpr  = lT >> 1;
    const int tHv  = (lT & 1) * 16;
    const int colS = tid >> 1;
    const int sS   = tid & 1;

    issue_prefetch(0, 0);

    #pragma unroll 1
    for (int np = 0; np < NITER; ++np) {
        const int buf = np & 1;
        const int n0 = ng0 + 4 * np;

        if (np + 1 < NITER) {
            issue_prefetch(np + 1, buf ^ 1);
            asm volatile("cp.async.wait_group 1;" ::: "memory");
        } else {
            asm volatile("cp.async.wait_group 0;" ::: "memory");
        }

        for (int i = tid; i < 576; i += 256) {
            const int region = i / 288, r = i - region * 288;
            const int nq = r / 72, rr = (r / 36) % 2, seg = r % 36;
            char* base = smem + (region ? ESL : ES);
            *(uint32_t*)(base + (nq * 34 + (rr ? 33 : 0)) * RW + seg * 4) = 0u;
        }
        __syncthreads();

        // ---- theta + relu + split -> S ----
        {
            const int ci0 = cig * 32;
            float sacc[32];
            #pragma unroll
            for (int j = 0; j < 32; ++j) sacc[j] = 0.f;
            #pragma unroll
            for (int k = 0; k < Kk; ++k)
                #pragma unroll
                for (int f = 0; f < Ff; ++f) {
                    const float yv = smf[EYK/4 + buf * 1152 + (nqT * 3 + k) * 96 + f * Tt + tTh];
                    const float* tp = &smf[ETH/4 + k * (Ff * Cc) + f * Cc + ci0];
                    #pragma unroll
                    for (int j = 0; j < 32; ++j) sacc[j] += yv * tp[j];
                }
            const uint32_t rowoff = (nqT * 34 + tTh + 1) * RW + ci0 * 2;
            uint32_t* dh = (uint32_t*)(smem + ES  + rowoff);
            uint32_t* dl = (uint32_t*)(smem + ESL + rowoff);
            #pragma unroll
            for (int jj = 0; jj < 16; ++jj) {
                const float v0 = fmaxf(sacc[2 * jj],     0.f);
                const float v1 = fmaxf(sacc[2 * jj + 1], 0.f);
                const __nv_bfloat16 h0 = __float2bfloat16(v0);
                const __nv_bfloat16 h1 = __float2bfloat16(v1);
                const __nv_bfloat16 l0 = __float2bfloat16(v0 - __bfloat162float(h0));
                const __nv_bfloat16 l1 = __float2bfloat16(v1 - __bfloat162float(h1));
                dh[jj] = (uint32_t)__bfloat16_as_ushort(h0)
                       | ((uint32_t)__bfloat16_as_ushort(h1) << 16);
                dl[jj] = (uint32_t)__bfloat16_as_ushort(l0)
                       | ((uint32_t)__bfloat16_as_ushort(l1) << 16);
            }
        }
        __syncthreads();

        // ---- conv GEMM ----
        float acc[2][4][4];
        #pragma unroll
        for (int i = 0; i < 2; ++i)
            #pragma unroll
            for (int j = 0; j < 4; ++j)
                #pragma unroll
                for (int q = 0; q < 4; ++q) acc[i][j][q] = 0.f;

        #pragma unroll
        for (int tap = 0; tap < 3; ++tap) {
            #pragma unroll
            for (int ks = 0; ks < 4; ++ks) {
                const int kb = ks * 32 + lkb;
                uint32_t ah[2][4], al[2][4], bh[2][4], bl[2][4];
                #pragma unroll
                for (int mf = 0; mf < 2; ++mf) {
                    const uint32_t aoff = (tap * 64 + wm * 32 + mf * 16 + lrow) * RW + kb;
                    ldmx4(ah[mf], smb + EW  + aoff);
                    ldmx4(al[mf], smb + EWL + aoff);
                }
                #pragma unroll
                for (int cb = 0; cb < 2; ++cb) {
                    const uint32_t boff = (wn * 34 + cb * 16 + lrow + tap) * RW + kb;
                    ldmx4(bh[cb], smb + ES  + boff);
                    ldmx4(bl[cb], smb + ESL + boff);
                }
                #pragma unroll
                for (int mf = 0; mf < 2; ++mf)
                    #pragma unroll
                    for (int cb = 0; cb < 2; ++cb)
                        #pragma unroll
                        for (int sub = 0; sub < 2; ++sub) {
                            float* d = acc[mf][cb * 2 + sub];
                            mma16816(d, ah[mf], bh[cb][sub], bh[cb][sub + 2]);
                            mma16816(d, ah[mf], bl[cb][sub], bl[cb][sub + 2]);
                            mma16816(d, al[mf], bh[cb][sub], bh[cb][sub + 2]);
                        }
            }
        }
        __syncthreads();   // all S reads done -> safe to overlay po

        // ---- fused: bias + residual + relu in registers, write po ----
        {
            float* po = smf + EPO/4;
            const float* xs = &smf[EXS/4 + buf * 384 + wn * 96];
            #pragma unroll
            for (int mf = 0; mf < 2; ++mf) {
                #pragma unroll
                for (int rr = 0; rr < 2; ++rr) {
                    const int c = wm * 32 + mf * 16 + qrow + rr * 8;
                    const float w0 = smf[EWR/4 + 0 * 64 + c];
                    const float w1 = smf[EWR/4 + 1 * 64 + c];
                    const float w2 = smf[EWR/4 + 2 * 64 + c];
                    const float bi = smf[EBI/4 + c];
                    #pragma unroll
                    for (int nf = 0; nf < 4; ++nf) {
                        const int t0 = nf * 8 + qcol;
                        float v0 = acc[mf][nf][rr * 2 + 0] + bi
                                 + w0 * xs[t0] + w1 * xs[32 + t0] + w2 * xs[64 + t0];
                        float v1 = acc[mf][nf][rr * 2 + 1] + bi
                                 + w0 * xs[t0 + 1] + w1 * xs[32 + t0 + 1] + w2 * xs[64 + t0 + 1];
                        *(float2*)&po[c * POW + wn * 32 + t0] =
                            make_float2(fmaxf(v0, 0.f), fmaxf(v1, 0.f));
                    }
                }
            }
        }
        __syncthreads();

        // ---- LN stats ----
        {
            const float* po = smf + EPO/4;
            float sum = 0.f, sq = 0.f;
            #pragma unroll
            for (int q = 0; q < 32; ++q) {
                const float v = po[(sS * 32 + q) * POW + colS];
                sum += v; sq += v * v;
            }
            sum += __shfl_xor_sync(0xffffffffu, sum, 1);
            sq  += __shfl_xor_sync(0xffffffffu, sq,  1);
            if (sS == 0) {
                const float m = sum * (1.f / Ct);
                const float var = sq * (1.f / Ct) - m * m;
                smf[EMU/4 + colS] = m;
                smf[ERS/4 + colS] = rsqrtf(var + 1e-5f);
            }
        }
        __syncthreads();

        // ---- normalize (read po) + store ----
        {
            const float* po = smf + EPO/4;
            const int clo = 2 * cpr, chi = clo + 1;
            const float glo = smf[EGM/4 + clo], bl = smf[EBB/4 + clo];
            const float ghi = smf[EGM/4 + chi], bh = smf[EBB/4 + chi];
            float olo[16], ohi[16];
            #pragma unroll
            for (int j = 0; j < 16; ++j) {
                const int col = nqT * 32 + tHv + j;
                const float mu = smf[EMU/4 + col];
                const float rs = smf[ERS/4 + col];
                olo[j] = (po[clo * POW + col] - mu) * rs * glo + bl;
                ohi[j] = (po[chi * POW + col] - mu) * rs * ghi + bh;
            }
            float* obase = out + ((size_t)(b * Nn + n0 + nqT)) * Ct * Tt;
            #pragma unroll
            for (int q = 0; q < 4; ++q) {
                *(float4*)(obase + clo * Tt + tHv + q * 4) =
                    make_float4(olo[q*4], olo[q*4+1], olo[q*4+2], olo[q*4+3]);
                *(float4*)(obase + chi * Tt + tHv + q * 4) =
                    make_float4(ohi[q*4], ohi[q*4+1], ohi[q*4+2], ohi[q*4+3]);
            }
        }
        __syncthreads();
    }
}

// ---------------------------------------------------------------------------
extern "C" void kernel_launch(void* const* d_in, const int* in_sizes, int n_in,
                              void* d_out, int out_size)
{
    const float* x      = (const float*)d_in[0];
    const float* cheb   = (const float*)d_in[1];
    const float* theta  = (const float*)d_in[2];
    const float* w_time = (const float*)d_in[3];
    const float* b_time = (const float*)d_in[4];
    const float* w_res  = (const float*)d_in[5];
    const float* b_res  = (const float*)d_in[6];
    const float* gamma  = (const float*)d_in[7];
    const float* beta   = (const float*)d_in[8];
    float* out = (float*)d_out;

    cudaFuncSetAttribute(gemm_mma_kernel,
                         cudaFuncAttributeMaxDynamicSharedMemorySize, GEMM_SMEM);
    cudaFuncSetAttribute(fused_epi_tc,
                         cudaFuncAttributeMaxDynamicSharedMemorySize, ESMEM);

    prep_all<<<6198, 256>>>(cheb, x, w_time);
    gemm_mma_kernel<<<dim3(16, 3, 32), 128, GEMM_SMEM>>>();
    fused_epi_tc<<<dim3(Nn / GRP, Bb), 256, ESMEM>>>(
        x, theta, w_res, b_time, b_res, gamma, beta, out);
}